// round 3
// baseline (speedup 1.0000x reference)
#include <cuda_runtime.h>
#include <cuda_bf16.h>
#include <stdint.h>

#define BB 8
#define VV 64
#define TT 257
#define DD 256
#define HH 8
#define DH 32

#define XN_ELEMS (BB*VV*TT*DD)

// ---------------- scratch (static device globals; allocation-free) ----------------
__device__ __align__(128) __nv_bfloat16 g_xn[XN_ELEMS];          // LN output, bf16
__device__ __align__(128) float  g_xsum[BB*VV*DD];               // masked sum of xn
__device__ __align__(128) float  g_cnt[BB*VV];
__device__ __align__(128) float  g_q[BB*VV*DD];
__device__ __align__(128) float  g_k[BB*VV*DD];
__device__ __align__(128) __nv_bfloat16 g_attn[BB*HH*VV*VV];     // softmax weights, bf16
__device__ __align__(128) __nv_bfloat16 g_wv[DD*DD];             // w_qkv rows 512..767 (row-major [e][c])
__device__ __align__(128) __nv_bfloat16 g_wp[DD*DD];             // w_proj             (row-major [e][c])
__device__ int g_maskkind;

// ---------------- mask dtype detection ----------------
// bool(1B): bytes at i%4!=0 are random 0/1.  int32: those bytes always 0.
// float32: high byte of value 1.0f is 0x3f.
__global__ void detect_mask_kind(const unsigned char* m) {
    if (threadIdx.x == 0 && blockIdx.x == 0) {
        int any = 0, isf = 0;
        for (int i = 0; i < 1024; i++) {
            unsigned char b1 = m[i*4+1], b2 = m[i*4+2], b3 = m[i*4+3];
            if (b1 | b2 | b3) any = 1;
            if (b3 == 0x3f) isf = 1;
        }
        g_maskkind = isf ? 2 : (any ? 1 : 0);
    }
}

__device__ __forceinline__ bool mask_at(const void* m, int idx, int kind) {
    if (kind == 0) return ((const int*)m)[idx] != 0;
    if (kind == 1) return ((const unsigned char*)m)[idx] != 0;
    return ((const float*)m)[idx] != 0.0f;
}

// ---------------- zero accumulators ----------------
__global__ void zero_kernel() {
    int i = blockIdx.x * 256 + threadIdx.x;
    if (i < BB*VV*DD) g_xsum[i] = 0.0f;
    if (i < BB*VV)    g_cnt[i]  = 0.0f;
}

// ---------------- weight conversion fp32 -> bf16 ----------------
__global__ void wconv_kernel(const float* w_qkv, const float* w_proj) {
    int i = blockIdx.x * 256 + threadIdx.x;
    if (i < DD*DD) {
        g_wv[i] = __float2bfloat16(w_qkv[2*DD*DD + i]);  // rows 512..767
        g_wp[i] = __float2bfloat16(w_proj[i]);
    }
}

// ---------------- LayerNorm + masked accumulation ----------------
// grid (512, 4): block = (b*64+v, t-chunk), 256 threads (one per feature)
__global__ void ln_kernel(const float* __restrict__ x, const void* __restrict__ obs_mask,
                          const float* __restrict__ ln_w, const float* __restrict__ ln_b) {
    int bv = blockIdx.x;
    int t0 = blockIdx.y * 65;
    int t1 = min(TT, t0 + 65);
    int d = threadIdx.x;
    int kind = g_maskkind;
    float w = ln_w[d], bb = ln_b[d];
    float acc = 0.0f, cnt = 0.0f;

    __shared__ float rs[8], rs2[8];
    __shared__ float s_mu, s_rstd;

    for (int t = t0; t < t1; t++) {
        size_t base = ((size_t)bv * TT + t) * DD;
        float v = x[base + d];
        float s = v, s2 = v * v;
        #pragma unroll
        for (int o = 16; o > 0; o >>= 1) {
            s  += __shfl_xor_sync(0xffffffffu, s, o);
            s2 += __shfl_xor_sync(0xffffffffu, s2, o);
        }
        if ((d & 31) == 0) { rs[d >> 5] = s; rs2[d >> 5] = s2; }
        __syncthreads();
        if (d == 0) {
            float S = 0.f, S2 = 0.f;
            #pragma unroll
            for (int i = 0; i < 8; i++) { S += rs[i]; S2 += rs2[i]; }
            float mu = S * (1.0f/256.0f);
            float var = S2 * (1.0f/256.0f) - mu * mu;
            s_mu = mu;
            s_rstd = rsqrtf(var + 1e-5f);
        }
        __syncthreads();
        float xn = (v - s_mu) * s_rstd * w + bb;
        g_xn[base + d] = __float2bfloat16(xn);
        bool mk = (t == 0) || mask_at(obs_mask, bv * (TT-1) + (t - 1), kind);
        if (mk) { acc += xn; cnt += 1.0f; }
    }
    atomicAdd(&g_xsum[bv * DD + d], acc);
    if (d == 0) atomicAdd(&g_cnt[bv], cnt);
}

// ---------------- q (t=0) and k (masked mean) projections ----------------
// grid 512 blocks (b*64+v), 256 threads
__global__ void qk_kernel(const float* __restrict__ w_qkv) {
    int bv = blockIdx.x;
    __shared__ float xn0[DD], xm[DD];
    int tid = threadIdx.x;
    xn0[tid] = __bfloat162float(g_xn[(size_t)bv * TT * DD + tid]);
    xm[tid]  = g_xsum[bv * DD + tid] / g_cnt[bv];
    __syncthreads();
    int warp = tid >> 5, lane = tid & 31;
    for (int e = warp; e < DD; e += 8) {
        const float4* wq = (const float4*)(w_qkv + (size_t)e * DD);
        const float4* wk = (const float4*)(w_qkv + (size_t)(DD + e) * DD);
        float q = 0.f, k = 0.f;
        #pragma unroll
        for (int i = lane; i < 64; i += 32) {
            float4 aq = wq[i], ak = wk[i];
            const float* xq = xn0 + i * 4;
            const float* xk = xm + i * 4;
            q += xq[0]*aq.x + xq[1]*aq.y + xq[2]*aq.z + xq[3]*aq.w;
            k += xk[0]*ak.x + xk[1]*ak.y + xk[2]*ak.z + xk[3]*ak.w;
        }
        #pragma unroll
        for (int o = 16; o > 0; o >>= 1) {
            q += __shfl_xor_sync(0xffffffffu, q, o);
            k += __shfl_xor_sync(0xffffffffu, k, o);
        }
        if (lane == 0) { g_q[bv * DD + e] = q; g_k[bv * DD + e] = k; }
    }
}

// ---------------- attention softmax over views ----------------
// grid 64 blocks = (b,h), 256 threads
__global__ void attn_kernel() {
    int b = blockIdx.x >> 3, h = blockIdx.x & 7;
    __shared__ float qs[VV][33], ks[VV][33];
    __shared__ float lg[VV][65];
    int tid = threadIdx.x;
    for (int i = tid; i < VV * DH; i += 256) {
        int v = i >> 5, dd = i & 31;
        qs[v][dd] = g_q[(b * VV + v) * DD + h * DH + dd];
        ks[v][dd] = g_k[(b * VV + v) * DD + h * DH + dd];
    }
    __syncthreads();
    const float scale = 0.17677669529663687f;  // 32^-0.5
    for (int p = tid; p < VV * VV; p += 256) {
        int i = p >> 6, j = p & 63;
        float s = 0.f;
        #pragma unroll
        for (int c = 0; c < DH; c++) s += qs[i][c] * ks[j][c];
        lg[i][j] = s * scale;
    }
    __syncthreads();
    int warp = tid >> 5, lane = tid & 31;
    for (int r = warp; r < VV; r += 8) {
        float v0 = lg[r][lane], v1 = lg[r][lane + 32];
        float m = fmaxf(v0, v1);
        #pragma unroll
        for (int o = 16; o > 0; o >>= 1) m = fmaxf(m, __shfl_xor_sync(0xffffffffu, m, o));
        float e0 = __expf(v0 - m), e1 = __expf(v1 - m);
        float s = e0 + e1;
        #pragma unroll
        for (int o = 16; o > 0; o >>= 1) s += __shfl_xor_sync(0xffffffffu, s, o);
        float inv = 1.0f / s;
        __nv_bfloat16* ap = g_attn + ((size_t)(b * HH + h) * VV + r) * VV;
        ap[lane]      = __float2bfloat16(e0 * inv);
        ap[lane + 32] = __float2bfloat16(e1 * inv);
    }
}

// ---------------- mma.sync helper ----------------
__device__ __forceinline__ void mma16816(float* c, const uint32_t* a, uint32_t b0, uint32_t b1) {
    asm volatile(
        "mma.sync.aligned.m16n8k16.row.col.f32.bf16.bf16.f32 "
        "{%0,%1,%2,%3}, {%4,%5,%6,%7}, {%8,%9}, {%0,%1,%2,%3};"
        : "+f"(c[0]), "+f"(c[1]), "+f"(c[2]), "+f"(c[3])
        : "r"(a[0]), "r"(a[1]), "r"(a[2]), "r"(a[3]), "r"(b0), "r"(b1));
}

// ---------------- fused V-GEMM -> per-head mix -> proj + residual ----------------
// grid (257, 8) = (t, b).  Block: 256 threads = 8 warps.
// smem: xn_s[64][264] (aliased as mixed_s), vf_t[256][66] (transposed), b_s[256][24]
#define XS 264
#define VS 66
#define BS 24
#define SMEM_TOTAL ((64*XS + 256*VS + 256*BS) * 2)

__global__ void __launch_bounds__(256)
fused_kernel(const float* __restrict__ x, const float* __restrict__ b_proj,
             float* __restrict__ out) {
    const int t = blockIdx.x;
    const int b = blockIdx.y;
    extern __shared__ __align__(16) unsigned char smem_raw[];
    __nv_bfloat16* xn_s = (__nv_bfloat16*)smem_raw;        // [64][XS], alias mixed_s
    __nv_bfloat16* vf_t = xn_s + 64 * XS;                  // [256][VS]  vf transposed [e][view]
    __nv_bfloat16* b_s  = vf_t + 256 * VS;                 // [256][BS]  weight k-tile [e][c]

    const int tid  = threadIdx.x;
    const int warp = tid >> 5, lane = tid & 31;
    const int g = lane >> 2, tg = lane & 3;
    const int wm = (warp & 1) * 32;       // phase0/2 warp m offset
    const int wn = (warp >> 1) * 64;      // phase0/2 warp n offset

    // ---- load xn tile: 64 views x 256 features at this (b,t) ----
    for (int i = tid; i < 64 * 32; i += 256) {
        int r = i >> 5, qx = i & 31;
        const uint4* src = (const uint4*)(g_xn + ((size_t)(b * VV + r) * TT + t) * DD) + qx;
        *((uint4*)(xn_s + r * XS) + qx) = *src;
    }
    __syncthreads();

    // =========== Phase 0: vf = xn @ Wv^T  (64x256x256) ===========
    {
        float acc[2][8][4];
        #pragma unroll
        for (int mi = 0; mi < 2; mi++)
            #pragma unroll
            for (int ni = 0; ni < 8; ni++)
                #pragma unroll
                for (int k = 0; k < 4; k++) acc[mi][ni][k] = 0.f;

        for (int k0 = 0; k0 < DD; k0 += 16) {
            {   // B tile: Wv[e][k0..k0+15], thread = row e
                const uint4* src = (const uint4*)(g_wv + tid * DD + k0);
                uint4 v0 = src[0], v1 = src[1];
                uint4* dst = (uint4*)(b_s + tid * BS);
                dst[0] = v0; dst[1] = v1;
            }
            __syncthreads();
            uint32_t a[2][4];
            #pragma unroll
            for (int mi = 0; mi < 2; mi++) {
                const __nv_bfloat16* ap = xn_s + (wm + mi*16 + g) * XS + k0 + tg*2;
                a[mi][0] = *(const uint32_t*)(ap);
                a[mi][1] = *(const uint32_t*)(ap + 8 * XS);
                a[mi][2] = *(const uint32_t*)(ap + 8);
                a[mi][3] = *(const uint32_t*)(ap + 8 * XS + 8);
            }
            #pragma unroll
            for (int ni = 0; ni < 8; ni++) {
                const __nv_bfloat16* bp = b_s + (wn + ni*8 + g) * BS + tg*2;
                uint32_t b0 = *(const uint32_t*)(bp);
                uint32_t b1 = *(const uint32_t*)(bp + 8);
                mma16816(acc[0][ni], a[0], b0, b1);
                mma16816(acc[1][ni], a[1], b0, b1);
            }
            __syncthreads();
        }
        // epilogue: write transposed vf_t[e][view]
        #pragma unroll
        for (int mi = 0; mi < 2; mi++)
            #pragma unroll
            for (int ni = 0; ni < 8; ni++) {
                int m = wm + mi*16 + g;
                int e = wn + ni*8 + tg*2;
                vf_t[(e    ) * VS + m    ] = __float2bfloat16(acc[mi][ni][0]);
                vf_t[(e + 1) * VS + m    ] = __float2bfloat16(acc[mi][ni][1]);
                vf_t[(e    ) * VS + m + 8] = __float2bfloat16(acc[mi][ni][2]);
                vf_t[(e + 1) * VS + m + 8] = __float2bfloat16(acc[mi][ni][3]);
            }
    }
    __syncthreads();

    // =========== Phase 1: mixed = attn_h @ vf_h  (warp h: 64x32x64) ===========
    {
        float macc[4][4][4];
        #pragma unroll
        for (int mi = 0; mi < 4; mi++)
            #pragma unroll
            for (int ni = 0; ni < 4; ni++)
                #pragma unroll
                for (int k = 0; k < 4; k++) macc[mi][ni][k] = 0.f;

        const __nv_bfloat16* attn_p = g_attn + (size_t)(b * HH + warp) * VV * VV;
        #pragma unroll
        for (int ks = 0; ks < 4; ks++) {
            int kk = ks * 16;
            uint32_t a[4][4];
            #pragma unroll
            for (int mi = 0; mi < 4; mi++) {
                const __nv_bfloat16* ap = attn_p + (mi*16 + g) * VV + kk + tg*2;
                a[mi][0] = *(const uint32_t*)(ap);
                a[mi][1] = *(const uint32_t*)(ap + 8 * VV);
                a[mi][2] = *(const uint32_t*)(ap + 8);
                a[mi][3] = *(const uint32_t*)(ap + 8 * VV + 8);
            }
            #pragma unroll
            for (int ni = 0; ni < 4; ni++) {
                const __nv_bfloat16* bp = vf_t + (warp * DH + ni*8 + g) * VS + kk + tg*2;
                uint32_t b0 = *(const uint32_t*)(bp);
                uint32_t b1 = *(const uint32_t*)(bp + 8);
                #pragma unroll
                for (int mi = 0; mi < 4; mi++) mma16816(macc[mi][ni], a[mi], b0, b1);
            }
        }
        // epilogue: mixed_s (alias of xn_s, safe: all phase-0 reads done)
        #pragma unroll
        for (int mi = 0; mi < 4; mi++)
            #pragma unroll
            for (int ni = 0; ni < 4; ni++) {
                int m = mi*16 + g;
                int n = warp * DH + ni*8 + tg*2;
                __nv_bfloat162 p01 = __floats2bfloat162_rn(macc[mi][ni][0], macc[mi][ni][1]);
                __nv_bfloat162 p23 = __floats2bfloat162_rn(macc[mi][ni][2], macc[mi][ni][3]);
                *(__nv_bfloat162*)(xn_s + m * XS + n)       = p01;
                *(__nv_bfloat162*)(xn_s + (m + 8) * XS + n) = p23;
            }
    }
    __syncthreads();

    // =========== Phase 2: out = mixed @ Wp^T + b_proj + x ===========
    {
        float acc[2][8][4];
        #pragma unroll
        for (int mi = 0; mi < 2; mi++)
            #pragma unroll
            for (int ni = 0; ni < 8; ni++)
                #pragma unroll
                for (int k = 0; k < 4; k++) acc[mi][ni][k] = 0.f;

        for (int k0 = 0; k0 < DD; k0 += 16) {
            {
                const uint4* src = (const uint4*)(g_wp + tid * DD + k0);
                uint4 v0 = src[0], v1 = src[1];
                uint4* dst = (uint4*)(b_s + tid * BS);
                dst[0] = v0; dst[1] = v1;
            }
            __syncthreads();
            uint32_t a[2][4];
            #pragma unroll
            for (int mi = 0; mi < 2; mi++) {
                const __nv_bfloat16* ap = xn_s + (wm + mi*16 + g) * XS + k0 + tg*2;
                a[mi][0] = *(const uint32_t*)(ap);
                a[mi][1] = *(const uint32_t*)(ap + 8 * XS);
                a[mi][2] = *(const uint32_t*)(ap + 8);
                a[mi][3] = *(const uint32_t*)(ap + 8 * XS + 8);
            }
            #pragma unroll
            for (int ni = 0; ni < 8; ni++) {
                const __nv_bfloat16* bp = b_s + (wn + ni*8 + g) * BS + tg*2;
                uint32_t b0 = *(const uint32_t*)(bp);
                uint32_t b1 = *(const uint32_t*)(bp + 8);
                mma16816(acc[0][ni], a[0], b0, b1);
                mma16816(acc[1][ni], a[1], b0, b1);
            }
            __syncthreads();
        }
        // epilogue: bias + residual, write fp32 output
        #pragma unroll
        for (int mi = 0; mi < 2; mi++)
            #pragma unroll
            for (int ni = 0; ni < 8; ni++) {
                int q = wm + mi*16 + g;
                int e = wn + ni*8 + tg*2;
                float bp0 = b_proj[e], bp1 = b_proj[e + 1];
                size_t base  = ((size_t)(b * VV + q) * TT + t) * DD + e;
                size_t base8 = base + (size_t)8 * TT * DD;
                out[base]      = acc[mi][ni][0] + bp0 + x[base];
                out[base + 1]  = acc[mi][ni][1] + bp1 + x[base + 1];
                out[base8]     = acc[mi][ni][2] + bp0 + x[base8];
                out[base8 + 1] = acc[mi][ni][3] + bp1 + x[base8 + 1];
            }
    }
}

// ---------------- launch ----------------
extern "C" void kernel_launch(void* const* d_in, const int* in_sizes, int n_in,
                              void* d_out, int out_size) {
    const float* x        = (const float*)d_in[0];
    const void*  obs_mask = d_in[1];
    const float* ln_w     = (const float*)d_in[2];
    const float* ln_b     = (const float*)d_in[3];
    const float* w_qkv    = (const float*)d_in[4];
    const float* w_proj   = (const float*)d_in[5];
    const float* b_proj   = (const float*)d_in[6];
    float* out = (float*)d_out;

    cudaFuncSetAttribute(fused_kernel, cudaFuncAttributeMaxDynamicSharedMemorySize, SMEM_TOTAL);

    detect_mask_kind<<<1, 32>>>((const unsigned char*)obs_mask);
    zero_kernel<<<512, 256>>>();
    wconv_kernel<<<256, 256>>>(w_qkv, w_proj);
    ln_kernel<<<dim3(BB*VV, 4), 256>>>(x, obs_mask, ln_w, ln_b);
    qk_kernel<<<BB*VV, 256>>>(w_qkv);
    attn_kernel<<<BB*HH, 256>>>();
    fused_kernel<<<dim3(TT, BB), 256, SMEM_TOTAL>>>(x, b_proj, out);
}

// round 5
// speedup vs baseline: 1.2021x; 1.2021x over previous
#include <cuda_runtime.h>
#include <cuda_bf16.h>
#include <stdint.h>

#define BB 8
#define VV 64
#define TT 257
#define DD 256
#define HH 8
#define DH 32

#define XN_ELEMS (BB*VV*TT*DD)

// ---------------- scratch (static device globals; allocation-free) ----------------
__device__ __align__(128) __nv_bfloat16 g_xn[XN_ELEMS];          // LN output, bf16
__device__ __align__(128) float  g_xsum[BB*VV*DD];               // masked sum of xn
__device__ __align__(128) float  g_cnt[BB*VV];
__device__ __align__(128) float  g_q[BB*VV*DD];
__device__ __align__(128) float  g_k[BB*VV*DD];
__device__ __align__(128) __nv_bfloat16 g_attn[BB*HH*VV*VV];     // softmax weights, bf16
__device__ __align__(128) __nv_bfloat16 g_wv[DD*DD];             // w_qkv rows 512..767 (row-major [e][c])
__device__ __align__(128) __nv_bfloat16 g_wp[DD*DD];             // w_proj             (row-major [e][c])
__device__ int g_maskkind;

// ---------------- mask dtype detection ----------------
__global__ void detect_mask_kind(const unsigned char* m) {
    if (threadIdx.x == 0 && blockIdx.x == 0) {
        int any = 0, isf = 0;
        for (int i = 0; i < 1024; i++) {
            unsigned char b1 = m[i*4+1], b2 = m[i*4+2], b3 = m[i*4+3];
            if (b1 | b2 | b3) any = 1;
            if (b3 == 0x3f) isf = 1;
        }
        g_maskkind = isf ? 2 : (any ? 1 : 0);
    }
}

__device__ __forceinline__ bool mask_at(const void* m, int idx, int kind) {
    if (kind == 0) return ((const int*)m)[idx] != 0;
    if (kind == 1) return ((const unsigned char*)m)[idx] != 0;
    return ((const float*)m)[idx] != 0.0f;
}

// ---------------- zero accumulators ----------------
__global__ void zero_kernel() {
    int i = blockIdx.x * 256 + threadIdx.x;
    if (i < BB*VV*DD) g_xsum[i] = 0.0f;
    if (i < BB*VV)    g_cnt[i]  = 0.0f;
}

// ---------------- weight conversion fp32 -> bf16 ----------------
__global__ void wconv_kernel(const float* w_qkv, const float* w_proj) {
    int i = blockIdx.x * 256 + threadIdx.x;
    if (i < DD*DD) {
        g_wv[i] = __float2bfloat16(w_qkv[2*DD*DD + i]);  // rows 512..767
        g_wp[i] = __float2bfloat16(w_proj[i]);
    }
}

// ---------------- LayerNorm: warp-per-row, barrier-free ----------------
// grid (512, 4): (b*64+v, t-chunk of 65). 256 threads = 8 warps; warp w owns
// t = t0+w, t0+w+8, ...  Each lane holds 8 features (2x float4).
__global__ void __launch_bounds__(256)
ln_kernel(const float* __restrict__ x, const void* __restrict__ obs_mask,
          const float* __restrict__ ln_w, const float* __restrict__ ln_b) {
    int bv = blockIdx.x;
    int t0 = blockIdx.y * 65;
    int t1 = min(TT, t0 + 65);
    int warp = threadIdx.x >> 5, lane = threadIdx.x & 31;
    int kind = g_maskkind;

    float4 w0  = *(const float4*)(ln_w + lane*4);
    float4 w1  = *(const float4*)(ln_w + 128 + lane*4);
    float4 lb0 = *(const float4*)(ln_b + lane*4);
    float4 lb1 = *(const float4*)(ln_b + 128 + lane*4);

    float acc[8];
    #pragma unroll
    for (int i = 0; i < 8; i++) acc[i] = 0.0f;
    float cnt = 0.0f;

    for (int t = t0 + warp; t < t1; t += 8) {
        size_t base = ((size_t)bv * TT + t) * DD;
        float4 v0 = *(const float4*)(x + base + lane*4);
        float4 v1 = *(const float4*)(x + base + 128 + lane*4);
        float s  = v0.x + v0.y + v0.z + v0.w + v1.x + v1.y + v1.z + v1.w;
        float s2 = v0.x*v0.x + v0.y*v0.y + v0.z*v0.z + v0.w*v0.w
                 + v1.x*v1.x + v1.y*v1.y + v1.z*v1.z + v1.w*v1.w;
        #pragma unroll
        for (int o = 16; o > 0; o >>= 1) {
            s  += __shfl_xor_sync(0xffffffffu, s, o);
            s2 += __shfl_xor_sync(0xffffffffu, s2, o);
        }
        float mu  = s * (1.0f/256.0f);
        float var = s2 * (1.0f/256.0f) - mu * mu;
        float rstd = rsqrtf(var + 1e-5f);

        float xn[8];
        xn[0] = (v0.x - mu) * rstd * w0.x + lb0.x;
        xn[1] = (v0.y - mu) * rstd * w0.y + lb0.y;
        xn[2] = (v0.z - mu) * rstd * w0.z + lb0.z;
        xn[3] = (v0.w - mu) * rstd * w0.w + lb0.w;
        xn[4] = (v1.x - mu) * rstd * w1.x + lb1.x;
        xn[5] = (v1.y - mu) * rstd * w1.y + lb1.y;
        xn[6] = (v1.z - mu) * rstd * w1.z + lb1.z;
        xn[7] = (v1.w - mu) * rstd * w1.w + lb1.w;

        __nv_bfloat162 p0 = __floats2bfloat162_rn(xn[0], xn[1]);
        __nv_bfloat162 p1 = __floats2bfloat162_rn(xn[2], xn[3]);
        __nv_bfloat162 p2 = __floats2bfloat162_rn(xn[4], xn[5]);
        __nv_bfloat162 p3 = __floats2bfloat162_rn(xn[6], xn[7]);
        uint2 u0; u0.x = *(uint32_t*)&p0; u0.y = *(uint32_t*)&p1;
        uint2 u1; u1.x = *(uint32_t*)&p2; u1.y = *(uint32_t*)&p3;
        *(uint2*)(g_xn + base + lane*4)       = u0;
        *(uint2*)(g_xn + base + 128 + lane*4) = u1;

        bool mk = (t == 0) || mask_at(obs_mask, bv * (TT-1) + (t - 1), kind);
        if (mk) {
            #pragma unroll
            for (int i = 0; i < 8; i++) acc[i] += xn[i];
            cnt += 1.0f;
        }
    }

    float* xs = g_xsum + bv * DD;
    #pragma unroll
    for (int i = 0; i < 4; i++) atomicAdd(xs + lane*4 + i, acc[i]);
    #pragma unroll
    for (int i = 0; i < 4; i++) atomicAdd(xs + 128 + lane*4 + i, acc[4 + i]);
    if (lane == 0) atomicAdd(&g_cnt[bv], cnt);
}

// ---------------- q (t=0) and k (masked mean) projections ----------------
__global__ void qk_kernel(const float* __restrict__ w_qkv) {
    int bv = blockIdx.x;
    __shared__ float xn0[DD], xm[DD];
    int tid = threadIdx.x;
    xn0[tid] = __bfloat162float(g_xn[(size_t)bv * TT * DD + tid]);
    xm[tid]  = g_xsum[bv * DD + tid] / g_cnt[bv];
    __syncthreads();
    int warp = tid >> 5, lane = tid & 31;
    for (int e = warp; e < DD; e += 8) {
        const float4* wq = (const float4*)(w_qkv + (size_t)e * DD);
        const float4* wk = (const float4*)(w_qkv + (size_t)(DD + e) * DD);
        float q = 0.f, k = 0.f;
        #pragma unroll
        for (int i = lane; i < 64; i += 32) {
            float4 aq = wq[i], ak = wk[i];
            const float* xq = xn0 + i * 4;
            const float* xk = xm + i * 4;
            q += xq[0]*aq.x + xq[1]*aq.y + xq[2]*aq.z + xq[3]*aq.w;
            k += xk[0]*ak.x + xk[1]*ak.y + xk[2]*ak.z + xk[3]*ak.w;
        }
        #pragma unroll
        for (int o = 16; o > 0; o >>= 1) {
            q += __shfl_xor_sync(0xffffffffu, q, o);
            k += __shfl_xor_sync(0xffffffffu, k, o);
        }
        if (lane == 0) { g_q[bv * DD + e] = q; g_k[bv * DD + e] = k; }
    }
}

// ---------------- attention softmax over views ----------------
__global__ void attn_kernel() {
    int b = blockIdx.x >> 3, h = blockIdx.x & 7;
    __shared__ float qs[VV][33], ks[VV][33];
    __shared__ float lg[VV][65];
    int tid = threadIdx.x;
    for (int i = tid; i < VV * DH; i += 256) {
        int v = i >> 5, dd = i & 31;
        qs[v][dd] = g_q[(b * VV + v) * DD + h * DH + dd];
        ks[v][dd] = g_k[(b * VV + v) * DD + h * DH + dd];
    }
    __syncthreads();
    const float scale = 0.17677669529663687f;
    for (int p = tid; p < VV * VV; p += 256) {
        int i = p >> 6, j = p & 63;
        float s = 0.f;
        #pragma unroll
        for (int c = 0; c < DH; c++) s += qs[i][c] * ks[j][c];
        lg[i][j] = s * scale;
    }
    __syncthreads();
    int warp = tid >> 5, lane = tid & 31;
    for (int r = warp; r < VV; r += 8) {
        float v0 = lg[r][lane], v1 = lg[r][lane + 32];
        float m = fmaxf(v0, v1);
        #pragma unroll
        for (int o = 16; o > 0; o >>= 1) m = fmaxf(m, __shfl_xor_sync(0xffffffffu, m, o));
        float e0 = __expf(v0 - m), e1 = __expf(v1 - m);
        float s = e0 + e1;
        #pragma unroll
        for (int o = 16; o > 0; o >>= 1) s += __shfl_xor_sync(0xffffffffu, s, o);
        float inv = 1.0f / s;
        __nv_bfloat16* ap = g_attn + ((size_t)(b * HH + h) * VV + r) * VV;
        ap[lane]      = __float2bfloat16(e0 * inv);
        ap[lane + 32] = __float2bfloat16(e1 * inv);
    }
}

// ---------------- mma / cp.async helpers ----------------
__device__ __forceinline__ void mma16816(float* c, const uint32_t* a, uint32_t b0, uint32_t b1) {
    asm volatile(
        "mma.sync.aligned.m16n8k16.row.col.f32.bf16.bf16.f32 "
        "{%0,%1,%2,%3}, {%4,%5,%6,%7}, {%8,%9}, {%0,%1,%2,%3};"
        : "+f"(c[0]), "+f"(c[1]), "+f"(c[2]), "+f"(c[3])
        : "r"(a[0]), "r"(a[1]), "r"(a[2]), "r"(a[3]), "r"(b0), "r"(b1));
}

__device__ __forceinline__ void cp_async16(void* smem, const void* gmem) {
    uint32_t s = (uint32_t)__cvta_generic_to_shared(smem);
    asm volatile("cp.async.cg.shared.global [%0], [%1], 16;\n" :: "r"(s), "l"(gmem));
}
#define CP_COMMIT() asm volatile("cp.async.commit_group;\n" ::: "memory")
#define CP_WAIT1()  asm volatile("cp.async.wait_group 1;\n" ::: "memory")
#define CP_WAIT0()  asm volatile("cp.async.wait_group 0;\n" ::: "memory")

// ---------------- fused V-GEMM -> per-head mix -> proj + residual ----------------
// grid (257, 8) = (t, b).  256 threads = 8 warps.
// smem: xn_s[64][XS] (aliased as mixed_s), vf_t[256][VS], b_s[2][256][BS] (double-buffered k-chunks of 32)
#define XS 264
#define VS 66
#define BS 40
#define KC 32
#define NKC (DD/KC)
#define SMEM_TOTAL ((64*XS + 256*VS + 2*256*BS) * 2)

__global__ void __launch_bounds__(256)
fused_kernel(const float* __restrict__ x, const float* __restrict__ b_proj,
             float* __restrict__ out) {
    const int t = blockIdx.x;
    const int b = blockIdx.y;
    extern __shared__ __align__(16) unsigned char smem_raw[];
    __nv_bfloat16* xn_s = (__nv_bfloat16*)smem_raw;        // [64][XS], alias mixed_s
    __nv_bfloat16* vf_t = xn_s + 64 * XS;                  // [256][VS]  vf transposed [e][view]
    __nv_bfloat16* b_s  = vf_t + 256 * VS;                 // [2][256][BS]

    const int tid  = threadIdx.x;
    const int warp = tid >> 5, lane = tid & 31;
    const int g = lane >> 2, tg = lane & 3;
    const int wm = (warp & 1) * 32;
    const int wn = (warp >> 1) * 64;

    // ---- load xn tile: 64 views x 256 features at this (b,t) ----
    for (int i = tid; i < 64 * 32; i += 256) {
        int r = i >> 5, qx = i & 31;
        const uint4* src = (const uint4*)(g_xn + ((size_t)(b * VV + r) * TT + t) * DD) + qx;
        *((uint4*)(xn_s + r * XS) + qx) = *src;
    }

    // =========== Phase 0: vf = xn @ Wv^T  (64x256x256) ===========
    {
        float acc[2][8][4];
        #pragma unroll
        for (int mi = 0; mi < 2; mi++)
            #pragma unroll
            for (int ni = 0; ni < 8; ni++)
                #pragma unroll
                for (int k = 0; k < 4; k++) acc[mi][ni][k] = 0.f;

        // prefetch chunk 0
        {
            const __nv_bfloat16* src = g_wv + tid * DD;
            __nv_bfloat16* dst = b_s + tid * BS;
            #pragma unroll
            for (int j = 0; j < 4; j++) cp_async16(dst + j*8, src + j*8);
            CP_COMMIT();
        }
        for (int kc = 0; kc < NKC; kc++) {
            if (kc + 1 < NKC) {
                int nbuf = (kc + 1) & 1;
                const __nv_bfloat16* src = g_wv + tid * DD + (kc + 1) * KC;
                __nv_bfloat16* dst = b_s + (nbuf * 256 + tid) * BS;
                #pragma unroll
                for (int j = 0; j < 4; j++) cp_async16(dst + j*8, src + j*8);
                CP_COMMIT();
                CP_WAIT1();
            } else {
                CP_WAIT0();
            }
            __syncthreads();
            const __nv_bfloat16* bbuf = b_s + (kc & 1) * 256 * BS;
            #pragma unroll
            for (int ks = 0; ks < 2; ks++) {
                int k0 = kc * KC + ks * 16;
                uint32_t a[2][4];
                #pragma unroll
                for (int mi = 0; mi < 2; mi++) {
                    const __nv_bfloat16* ap = xn_s + (wm + mi*16 + g) * XS + k0 + tg*2;
                    a[mi][0] = *(const uint32_t*)(ap);
                    a[mi][1] = *(const uint32_t*)(ap + 8 * XS);
                    a[mi][2] = *(const uint32_t*)(ap + 8);
                    a[mi][3] = *(const uint32_t*)(ap + 8 * XS + 8);
                }
                #pragma unroll
                for (int ni = 0; ni < 8; ni++) {
                    const __nv_bfloat16* bp = bbuf + (wn + ni*8 + g) * BS + ks*16 + tg*2;
                    uint32_t b0 = *(const uint32_t*)(bp);
                    uint32_t b1 = *(const uint32_t*)(bp + 8);
                    mma16816(acc[0][ni], a[0], b0, b1);
                    mma16816(acc[1][ni], a[1], b0, b1);
                }
            }
            __syncthreads();
        }
        // epilogue: write transposed vf_t[e][view]
        #pragma unroll
        for (int mi = 0; mi < 2; mi++)
            #pragma unroll
            for (int ni = 0; ni < 8; ni++) {
                int m = wm + mi*16 + g;
                int e = wn + ni*8 + tg*2;
                vf_t[(e    ) * VS + m    ] = __float2bfloat16(acc[mi][ni][0]);
                vf_t[(e + 1) * VS + m    ] = __float2bfloat16(acc[mi][ni][1]);
                vf_t[(e    ) * VS + m + 8] = __float2bfloat16(acc[mi][ni][2]);
                vf_t[(e + 1) * VS + m + 8] = __float2bfloat16(acc[mi][ni][3]);
            }
    }
    __syncthreads();

    // =========== Phase 1: mixed = attn_h @ vf_h  (warp h: 64x32x64) ===========
    {
        float macc[4][4][4];
        #pragma unroll
        for (int mi = 0; mi < 4; mi++)
            #pragma unroll
            for (int ni = 0; ni < 4; ni++)
                #pragma unroll
                for (int k = 0; k < 4; k++) macc[mi][ni][k] = 0.f;

        const __nv_bfloat16* attn_p = g_attn + (size_t)(b * HH + warp) * VV * VV;
        #pragma unroll
        for (int ks = 0; ks < 4; ks++) {
            int kk = ks * 16;
            uint32_t a[4][4];
            #pragma unroll
            for (int mi = 0; mi < 4; mi++) {
                const __nv_bfloat16* ap = attn_p + (mi*16 + g) * VV + kk + tg*2;
                a[mi][0] = *(const uint32_t*)(ap);
                a[mi][1] = *(const uint32_t*)(ap + 8 * VV);
                a[mi][2] = *(const uint32_t*)(ap + 8);
                a[mi][3] = *(const uint32_t*)(ap + 8 * VV + 8);
            }
            #pragma unroll
            for (int ni = 0; ni < 4; ni++) {
                const __nv_bfloat16* bp = vf_t + (warp * DH + ni*8 + g) * VS + kk + tg*2;
                uint32_t b0 = *(const uint32_t*)(bp);
                uint32_t b1 = *(const uint32_t*)(bp + 8);
                #pragma unroll
                for (int mi = 0; mi < 4; mi++) mma16816(macc[mi][ni], a[mi], b0, b1);
            }
        }
        __syncthreads();   // ensure all phase-1 reads of vf_t / xn_s done before aliasing write
        #pragma unroll
        for (int mi = 0; mi < 4; mi++)
            #pragma unroll
            for (int ni = 0; ni < 4; ni++) {
                int m = mi*16 + g;
                int n = warp * DH + ni*8 + tg*2;
                __nv_bfloat162 p01 = __floats2bfloat162_rn(macc[mi][ni][0], macc[mi][ni][1]);
                __nv_bfloat162 p23 = __floats2bfloat162_rn(macc[mi][ni][2], macc[mi][ni][3]);
                *(__nv_bfloat162*)(xn_s + m * XS + n)       = p01;
                *(__nv_bfloat162*)(xn_s + (m + 8) * XS + n) = p23;
            }
    }
    __syncthreads();

    // =========== Phase 2: out = mixed @ Wp^T + b_proj + x ===========
    {
        float acc[2][8][4];
        #pragma unroll
        for (int mi = 0; mi < 2; mi++)
            #pragma unroll
            for (int ni = 0; ni < 8; ni++)
                #pragma unroll
                for (int k = 0; k < 4; k++) acc[mi][ni][k] = 0.f;

        {
            const __nv_bfloat16* src = g_wp + tid * DD;
            __nv_bfloat16* dst = b_s + tid * BS;
            #pragma unroll
            for (int j = 0; j < 4; j++) cp_async16(dst + j*8, src + j*8);
            CP_COMMIT();
        }
        for (int kc = 0; kc < NKC; kc++) {
            if (kc + 1 < NKC) {
                int nbuf = (kc + 1) & 1;
                const __nv_bfloat16* src = g_wp + tid * DD + (kc + 1) * KC;
                __nv_bfloat16* dst = b_s + (nbuf * 256 + tid) * BS;
                #pragma unroll
                for (int j = 0; j < 4; j++) cp_async16(dst + j*8, src + j*8);
                CP_COMMIT();
                CP_WAIT1();
            } else {
                CP_WAIT0();
            }
            __syncthreads();
            const __nv_bfloat16* bbuf = b_s + (kc & 1) * 256 * BS;
            #pragma unroll
            for (int ks = 0; ks < 2; ks++) {
                int k0 = kc * KC + ks * 16;
                uint32_t a[2][4];
                #pragma unroll
                for (int mi = 0; mi < 2; mi++) {
                    const __nv_bfloat16* ap = xn_s + (wm + mi*16 + g) * XS + k0 + tg*2;
                    a[mi][0] = *(const uint32_t*)(ap);
                    a[mi][1] = *(const uint32_t*)(ap + 8 * XS);
                    a[mi][2] = *(const uint32_t*)(ap + 8);
                    a[mi][3] = *(const uint32_t*)(ap + 8 * XS + 8);
                }
                #pragma unroll
                for (int ni = 0; ni < 8; ni++) {
                    const __nv_bfloat16* bp = bbuf + (wn + ni*8 + g) * BS + ks*16 + tg*2;
                    uint32_t b0 = *(const uint32_t*)(bp);
                    uint32_t b1 = *(const uint32_t*)(bp + 8);
                    mma16816(acc[0][ni], a[0], b0, b1);
                    mma16816(acc[1][ni], a[1], b0, b1);
                }
            }
            __syncthreads();
        }
        // epilogue: bias + residual, fp32 output
        #pragma unroll
        for (int mi = 0; mi < 2; mi++)
            #pragma unroll
            for (int ni = 0; ni < 8; ni++) {
                int q = wm + mi*16 + g;
                int e = wn + ni*8 + tg*2;
                float bp0 = b_proj[e], bp1 = b_proj[e + 1];
                size_t base  = ((size_t)(b * VV + q) * TT + t) * DD + e;
                size_t base8 = base + (size_t)8 * TT * DD;
                out[base]      = acc[mi][ni][0] + bp0 + x[base];
                out[base + 1]  = acc[mi][ni][1] + bp1 + x[base + 1];
                out[base8]     = acc[mi][ni][2] + bp0 + x[base8];
                out[base8 + 1] = acc[mi][ni][3] + bp1 + x[base8 + 1];
            }
    }
}

// ---------------- launch ----------------
extern "C" void kernel_launch(void* const* d_in, const int* in_sizes, int n_in,
                              void* d_out, int out_size) {
    const float* x        = (const float*)d_in[0];
    const void*  obs_mask = d_in[1];
    const float* ln_w     = (const float*)d_in[2];
    const float* ln_b     = (const float*)d_in[3];
    const float* w_qkv    = (const float*)d_in[4];
    const float* w_proj   = (const float*)d_in[5];
    const float* b_proj   = (const float*)d_in[6];
    float* out = (float*)d_out;

    cudaFuncSetAttribute(fused_kernel, cudaFuncAttributeMaxDynamicSharedMemorySize, SMEM_TOTAL);

    detect_mask_kind<<<1, 32>>>((const unsigned char*)obs_mask);
    zero_kernel<<<512, 256>>>();
    wconv_kernel<<<256, 256>>>(w_qkv, w_proj);
    ln_kernel<<<dim3(BB*VV, 4), 256>>>(x, obs_mask, ln_w, ln_b);
    qk_kernel<<<BB*VV, 256>>>(w_qkv);
    attn_kernel<<<BB*HH, 256>>>();
    fused_kernel<<<dim3(TT, BB), 256, SMEM_TOTAL>>>(x, b_proj, out);
}

// round 10
// speedup vs baseline: 1.4712x; 1.2238x over previous
#include <cuda_runtime.h>
#include <cuda_bf16.h>
#include <stdint.h>

#define BB 8
#define VV 64
#define TT 257
#define DD 256
#define HH 8
#define DH 32

#define XN_ELEMS (BB*VV*TT*DD)

// ---------------- scratch ----------------
__device__ __align__(128) __nv_bfloat16 g_xn[XN_ELEMS];
__device__ __align__(128) float  g_xsum8[8*BB*VV*DD];   // per-y-block partial sums
__device__ __align__(128) float  g_cnt8[8*BB*VV];
__device__ __align__(128) float  g_q[BB*VV*DD];
__device__ __align__(128) float  g_k[BB*VV*DD];
__device__ __align__(128) __nv_bfloat16 g_attn[BB*HH*VV*VV];
__device__ __align__(128) __nv_bfloat16 g_wv[DD*DD];    // w_qkv rows 512..767 [e][k]
__device__ __align__(128) __nv_bfloat16 g_wp[DD*DD];    // w_proj [e][k]
__device__ int g_maskkind;

// ---------------- helpers ----------------
__device__ __forceinline__ uint32_t smem_u32(const void* p) {
    uint32_t a;
    asm("{ .reg .u64 t; cvta.to.shared.u64 t, %1; cvt.u32.u64 %0, t; }" : "=r"(a) : "l"(p));
    return a;
}
__device__ __forceinline__ void mma16816(float* c, const uint32_t* a, uint32_t b0, uint32_t b1) {
    asm volatile(
        "mma.sync.aligned.m16n8k16.row.col.f32.bf16.bf16.f32 "
        "{%0,%1,%2,%3}, {%4,%5,%6,%7}, {%8,%9}, {%0,%1,%2,%3};"
        : "+f"(c[0]), "+f"(c[1]), "+f"(c[2]), "+f"(c[3])
        : "r"(a[0]), "r"(a[1]), "r"(a[2]), "r"(a[3]), "r"(b0), "r"(b1));
}
__device__ __forceinline__ void ldm_x4(uint32_t* r, uint32_t addr) {
    asm volatile("ldmatrix.sync.aligned.m8n8.x4.shared.b16 {%0,%1,%2,%3}, [%4];"
        : "=r"(r[0]), "=r"(r[1]), "=r"(r[2]), "=r"(r[3]) : "r"(addr));
}
__device__ __forceinline__ void cp_async16(uint32_t smem, const void* gmem) {
    asm volatile("cp.async.cg.shared.global [%0], [%1], 16;\n" :: "r"(smem), "l"(gmem));
}
#define CP_COMMIT() asm volatile("cp.async.commit_group;\n" ::: "memory")
#define CP_WAIT1()  asm volatile("cp.async.wait_group 1;\n" ::: "memory")
#define CP_WAIT0()  asm volatile("cp.async.wait_group 0;\n" ::: "memory")

__device__ __forceinline__ bool mask_at(const void* m, int idx, int kind) {
    if (kind == 0) return ((const int*)m)[idx] != 0;
    if (kind == 1) return ((const unsigned char*)m)[idx] != 0;
    return ((const float*)m)[idx] != 0.0f;
}

// ---------------- prep: weight convert + mask dtype detect ----------------
__global__ void prep_kernel(const float* __restrict__ w_qkv, const float* __restrict__ w_proj,
                            const unsigned char* __restrict__ m) {
    int i = blockIdx.x * 256 + threadIdx.x;
    if (i < DD*DD) {
        g_wv[i] = __float2bfloat16(w_qkv[2*DD*DD + i]);
        g_wp[i] = __float2bfloat16(w_proj[i]);
    }
    if (blockIdx.x == 0 && threadIdx.x == 0) {
        int any = 0, isf = 0;
        for (int j = 0; j < 1024; j++) {
            unsigned char b1 = m[j*4+1], b2 = m[j*4+2], b3 = m[j*4+3];
            if (b1 | b2 | b3) any = 1;
            if (b3 == 0x3f) isf = 1;
        }
        g_maskkind = isf ? 2 : (any ? 1 : 0);
    }
}

// ---------------- LayerNorm: warp-per-row, no atomics ----------------
// grid (512, 8): block covers 33 t's; block-local reduction -> per-y partial slice.
__global__ void __launch_bounds__(256)
ln_kernel(const float* __restrict__ x, const void* __restrict__ obs_mask,
          const float* __restrict__ ln_w, const float* __restrict__ ln_b) {
    int bv = blockIdx.x;
    int y  = blockIdx.y;
    int t0 = y * 33;
    int t1 = min(TT, t0 + 33);
    int warp = threadIdx.x >> 5, lane = threadIdx.x & 31;
    int kind = g_maskkind;

    __shared__ float wsum[8][DD];
    __shared__ float wcnt[8];

    float4 w0  = *(const float4*)(ln_w + lane*4);
    float4 w1  = *(const float4*)(ln_w + 128 + lane*4);
    float4 lb0 = *(const float4*)(ln_b + lane*4);
    float4 lb1 = *(const float4*)(ln_b + 128 + lane*4);

    float acc[8];
    #pragma unroll
    for (int i = 0; i < 8; i++) acc[i] = 0.0f;
    float cnt = 0.0f;

    for (int t = t0 + warp; t < t1; t += 8) {
        size_t base = ((size_t)bv * TT + t) * DD;
        float4 v0 = *(const float4*)(x + base + lane*4);
        float4 v1 = *(const float4*)(x + base + 128 + lane*4);
        float s  = v0.x + v0.y + v0.z + v0.w + v1.x + v1.y + v1.z + v1.w;
        float s2 = v0.x*v0.x + v0.y*v0.y + v0.z*v0.z + v0.w*v0.w
                 + v1.x*v1.x + v1.y*v1.y + v1.z*v1.z + v1.w*v1.w;
        #pragma unroll
        for (int o = 16; o > 0; o >>= 1) {
            s  += __shfl_xor_sync(0xffffffffu, s, o);
            s2 += __shfl_xor_sync(0xffffffffu, s2, o);
        }
        float mu  = s * (1.0f/256.0f);
        float var = s2 * (1.0f/256.0f) - mu * mu;
        float rstd = rsqrtf(var + 1e-5f);

        float xn[8];
        xn[0] = (v0.x - mu) * rstd * w0.x + lb0.x;
        xn[1] = (v0.y - mu) * rstd * w0.y + lb0.y;
        xn[2] = (v0.z - mu) * rstd * w0.z + lb0.z;
        xn[3] = (v0.w - mu) * rstd * w0.w + lb0.w;
        xn[4] = (v1.x - mu) * rstd * w1.x + lb1.x;
        xn[5] = (v1.y - mu) * rstd * w1.y + lb1.y;
        xn[6] = (v1.z - mu) * rstd * w1.z + lb1.z;
        xn[7] = (v1.w - mu) * rstd * w1.w + lb1.w;

        __nv_bfloat162 p0 = __floats2bfloat162_rn(xn[0], xn[1]);
        __nv_bfloat162 p1 = __floats2bfloat162_rn(xn[2], xn[3]);
        __nv_bfloat162 p2 = __floats2bfloat162_rn(xn[4], xn[5]);
        __nv_bfloat162 p3 = __floats2bfloat162_rn(xn[6], xn[7]);
        uint2 u0; u0.x = *(uint32_t*)&p0; u0.y = *(uint32_t*)&p1;
        uint2 u1; u1.x = *(uint32_t*)&p2; u1.y = *(uint32_t*)&p3;
        *(uint2*)(g_xn + base + lane*4)       = u0;
        *(uint2*)(g_xn + base + 128 + lane*4) = u1;

        bool mk = (t == 0) || mask_at(obs_mask, bv * (TT-1) + (t - 1), kind);
        if (mk) {
            #pragma unroll
            for (int i = 0; i < 8; i++) acc[i] += xn[i];
            cnt += 1.0f;
        }
    }
    #pragma unroll
    for (int i = 0; i < 4; i++) {
        wsum[warp][lane*4 + i]       = acc[i];
        wsum[warp][128 + lane*4 + i] = acc[4 + i];
    }
    if (lane == 0) wcnt[warp] = cnt;
    __syncthreads();
    int tid = threadIdx.x;
    float S = 0.f;
    #pragma unroll
    for (int wv = 0; wv < 8; wv++) S += wsum[wv][tid];
    g_xsum8[(y * BB*VV + bv) * DD + tid] = S;
    if (tid == 0) {
        float C = 0.f;
        #pragma unroll
        for (int wv = 0; wv < 8; wv++) C += wcnt[wv];
        g_cnt8[y * BB*VV + bv] = C;
    }
}

// ---------------- q / k projections ----------------
__global__ void qk_kernel(const float* __restrict__ w_qkv) {
    int bv = blockIdx.x;
    __shared__ float xn0[DD], xm[DD];
    int tid = threadIdx.x;
    xn0[tid] = __bfloat162float(g_xn[(size_t)bv * TT * DD + tid]);
    {
        float S = 0.f, C = 0.f;
        #pragma unroll
        for (int y = 0; y < 8; y++) {
            S += g_xsum8[(y * BB*VV + bv) * DD + tid];
            C += g_cnt8[y * BB*VV + bv];
        }
        xm[tid] = S / C;
    }
    __syncthreads();
    int warp = tid >> 5, lane = tid & 31;
    for (int e = warp; e < DD; e += 8) {
        const float4* wq = (const float4*)(w_qkv + (size_t)e * DD);
        const float4* wk = (const float4*)(w_qkv + (size_t)(DD + e) * DD);
        float q = 0.f, k = 0.f;
        #pragma unroll
        for (int i = lane; i < 64; i += 32) {
            float4 aq = wq[i], ak = wk[i];
            const float* xq = xn0 + i * 4;
            const float* xk = xm + i * 4;
            q += xq[0]*aq.x + xq[1]*aq.y + xq[2]*aq.z + xq[3]*aq.w;
            k += xk[0]*ak.x + xk[1]*ak.y + xk[2]*ak.z + xk[3]*ak.w;
        }
        #pragma unroll
        for (int o = 16; o > 0; o >>= 1) {
            q += __shfl_xor_sync(0xffffffffu, q, o);
            k += __shfl_xor_sync(0xffffffffu, k, o);
        }
        if (lane == 0) { g_q[bv * DD + e] = q; g_k[bv * DD + e] = k; }
    }
}

// ---------------- attention softmax ----------------
__global__ void attn_kernel() {
    int b = blockIdx.x >> 3, h = blockIdx.x & 7;
    __shared__ float qs[VV][33], ks[VV][33];
    __shared__ float lg[VV][65];
    int tid = threadIdx.x;
    for (int i = tid; i < VV * DH; i += 256) {
        int v = i >> 5, dd = i & 31;
        qs[v][dd] = g_q[(b * VV + v) * DD + h * DH + dd];
        ks[v][dd] = g_k[(b * VV + v) * DD + h * DH + dd];
    }
    __syncthreads();
    const float scale = 0.17677669529663687f;
    for (int p = tid; p < VV * VV; p += 256) {
        int i = p >> 6, j = p & 63;
        float s = 0.f;
        #pragma unroll
        for (int c = 0; c < DH; c++) s += qs[i][c] * ks[j][c];
        lg[i][j] = s * scale;
    }
    __syncthreads();
    int warp = tid >> 5, lane = tid & 31;
    for (int r = warp; r < VV; r += 8) {
        float v0 = lg[r][lane], v1 = lg[r][lane + 32];
        float m = fmaxf(v0, v1);
        #pragma unroll
        for (int o = 16; o > 0; o >>= 1) m = fmaxf(m, __shfl_xor_sync(0xffffffffu, m, o));
        float e0 = __expf(v0 - m), e1 = __expf(v1 - m);
        float s = e0 + e1;
        #pragma unroll
        for (int o = 16; o > 0; o >>= 1) s += __shfl_xor_sync(0xffffffffu, s, o);
        float inv = 1.0f / s;
        __nv_bfloat16* ap = g_attn + ((size_t)(b * HH + h) * VV + r) * VV;
        ap[lane]      = __float2bfloat16(e0 * inv);
        ap[lane + 32] = __float2bfloat16(e1 * inv);
    }
}

// ---------------- fused V-GEMM -> mix -> proj (mma.sync + ldmatrix) ----------------
// grid (257, 8) = (t, b). 256 threads = 8 warps, 2 CTAs/SM.
// smem bytes:
//   [0, 33792)        A: xn/mixed [64][XS=264] bf16   (528B stride: ldmatrix conflict-free)
//   [33792, 74752)    B: weight chunks, 2 x [256][BS=40] bf16 (80B stride) ; reused fp32 out-stage
//   [74752, 108544)   vfT: [256][VS=66] bf16
#define XS 264
#define BS 40
#define VS 66
#define SM_A 0
#define SM_B 33792
#define SM_VFT 74752
#define BBUF 20480
#define SMEM_TOT 108544

__device__ __forceinline__ void stage_w(uint32_t smb, const __nv_bfloat16* W, int kc, int buf, int tid) {
    uint32_t dst = smb + SM_B + buf * BBUF + tid * (BS * 2);
    const __nv_bfloat16* src = W + tid * DD + kc * 32;
    #pragma unroll
    for (int j = 0; j < 4; j++) cp_async16(dst + j * 16, src + j * 8);
    CP_COMMIT();
}

// one 64x256x256 GEMM phase: acc += A(smem) @ W^T ; chunk0 must be staged+committed
__device__ __forceinline__ void gemm_phase(uint32_t smb, const __nv_bfloat16* __restrict__ W,
                                           float acc[2][8][4],
                                           const uint32_t aB0, const uint32_t aB1,
                                           const uint32_t* bB, int tid) {
    for (int kc = 0; kc < 8; kc++) {
        if (kc < 7) { stage_w(smb, W, kc + 1, (kc + 1) & 1, tid); CP_WAIT1(); }
        else        { CP_WAIT0(); }
        __syncthreads();
        uint32_t bufo = (uint32_t)((kc & 1) * BBUF);
        #pragma unroll
        for (int ks = 0; ks < 2; ks++) {
            uint32_t kbyte = (uint32_t)((kc * 32 + ks * 16) * 2);
            uint32_t a[2][4];
            ldm_x4(a[0], aB0 + kbyte);
            ldm_x4(a[1], aB1 + kbyte);
            #pragma unroll
            for (int p = 0; p < 4; p++) {
                uint32_t bf[4];
                ldm_x4(bf, bB[p] + bufo + (uint32_t)(ks * 32));
                mma16816(acc[0][2*p],   a[0], bf[0], bf[1]);
                mma16816(acc[1][2*p],   a[1], bf[0], bf[1]);
                mma16816(acc[0][2*p+1], a[0], bf[2], bf[3]);
                mma16816(acc[1][2*p+1], a[1], bf[2], bf[3]);
            }
        }
        __syncthreads();
    }
}

__global__ void __launch_bounds__(256, 2)
fused_kernel(const float* __restrict__ x, const float* __restrict__ b_proj,
             float* __restrict__ out) {
    const int t = blockIdx.x;
    const int b = blockIdx.y;
    extern __shared__ __align__(128) char sm[];
    const uint32_t smb = smem_u32(sm);
    __nv_bfloat16* xn_s = (__nv_bfloat16*)(sm + SM_A);
    __nv_bfloat16* vf_t = (__nv_bfloat16*)(sm + SM_VFT);

    const int tid  = threadIdx.x;
    const int warp = tid >> 5, lane = tid & 31;
    const int g = lane >> 2, tg = lane & 3;
    const int wm = (warp & 1) * 32;
    const int wn = (warp >> 1) * 64;

    // ldmatrix base addresses
    const int sel = lane >> 3;                       // 0..3
    uint32_t aB0, aB1, bB[4];
    {
        int arow = wm + (sel & 1) * 8 + (lane & 7);
        uint32_t abase = smb + SM_A + (uint32_t)((arow * XS + (sel >> 1) * 8) * 2);
        aB0 = abase;
        aB1 = abase + (uint32_t)(16 * XS * 2);
        int n_off = (lane >> 4) * 8 + (lane & 7);
        int kb = ((lane >> 3) & 1) * 8;
        #pragma unroll
        for (int p = 0; p < 4; p++)
            bB[p] = smb + SM_B + (uint32_t)(((wn + p * 16 + n_off) * BS + kb) * 2);
    }

    // stage A (xn tile) + W chunk 0 (one group each, in this order)
    {
        #pragma unroll
        for (int it = 0; it < 8; it++) {
            int idx = it * 256 + tid;          // 0..2047
            int row = idx >> 5, c16 = idx & 31;
            uint32_t dst = smb + SM_A + (uint32_t)(row * XS * 2 + c16 * 16);
            const void* src = g_xn + ((size_t)(b * VV + row) * TT + t) * DD + c16 * 8;
            cp_async16(dst, src);
        }
        CP_COMMIT();
    }
    stage_w(smb, g_wv, 0, 0, tid);

    // ===== Phase 0: vf = xn @ Wv^T =====
    float acc[2][8][4];
    #pragma unroll
    for (int mi = 0; mi < 2; mi++)
        #pragma unroll
        for (int ni = 0; ni < 8; ni++)
            #pragma unroll
            for (int k = 0; k < 4; k++) acc[mi][ni][k] = 0.f;
    gemm_phase(smb, g_wv, acc, aB0, aB1, bB, tid);

    // epilogue 0: acc -> vfT[e][m] (bf16 transposed)
    #pragma unroll
    for (int mi = 0; mi < 2; mi++)
        #pragma unroll
        for (int ni = 0; ni < 8; ni++) {
            int m = wm + mi * 16 + g;
            int e = wn + ni * 8 + tg * 2;
            vf_t[(e    ) * VS + m    ] = __float2bfloat16(acc[mi][ni][0]);
            vf_t[(e + 1) * VS + m    ] = __float2bfloat16(acc[mi][ni][1]);
            vf_t[(e    ) * VS + m + 8] = __float2bfloat16(acc[mi][ni][2]);
            vf_t[(e + 1) * VS + m + 8] = __float2bfloat16(acc[mi][ni][3]);
        }
    __syncthreads();

    // ===== Mix: mixed = attn_h @ vf_h  (warp h: 64x32x64) =====
    {
        float macc[4][4][4];
        #pragma unroll
        for (int mi = 0; mi < 4; mi++)
            #pragma unroll
            for (int ni = 0; ni < 4; ni++)
                #pragma unroll
                for (int k = 0; k < 4; k++) macc[mi][ni][k] = 0.f;

        const __nv_bfloat16* attn_p = g_attn + (size_t)(b * HH + warp) * VV * VV;
        #pragma unroll
        for (int ks = 0; ks < 4; ks++) {
            int kk = ks * 16;
            uint32_t a[4][4];
            #pragma unroll
            for (int mi = 0; mi < 4; mi++) {
                const __nv_bfloat16* ap = attn_p + (mi*16 + g) * VV + kk + tg*2;
                a[mi][0] = *(const uint32_t*)(ap);
                a[mi][1] = *(const uint32_t*)(ap + 8 * VV);
                a[mi][2] = *(const uint32_t*)(ap + 8);
                a[mi][3] = *(const uint32_t*)(ap + 8 * VV + 8);
            }
            #pragma unroll
            for (int ni = 0; ni < 4; ni++) {
                const __nv_bfloat16* bp = vf_t + (warp * DH + ni*8 + g) * VS + kk + tg*2;
                uint32_t b0 = *(const uint32_t*)(bp);
                uint32_t b1 = *(const uint32_t*)(bp + 8);
                #pragma unroll
                for (int mi = 0; mi < 4; mi++) mma16816(macc[mi][ni], a[mi], b0, b1);
            }
        }
        __syncthreads();   // all reads of xn_s/vf_t done before aliasing write
        #pragma unroll
        for (int mi = 0; mi < 4; mi++)
            #pragma unroll
            for (int ni = 0; ni < 4; ni++) {
                int m = mi*16 + g;
                int n = warp * DH + ni*8 + tg*2;
                __nv_bfloat162 p01 = __floats2bfloat162_rn(macc[mi][ni][0], macc[mi][ni][1]);
                __nv_bfloat162 p23 = __floats2bfloat162_rn(macc[mi][ni][2], macc[mi][ni][3]);
                *(__nv_bfloat162*)(xn_s + m * XS + n)       = p01;
                *(__nv_bfloat162*)(xn_s + (m + 8) * XS + n) = p23;
            }
    }
    __syncthreads();

    // ===== Phase 2: out = mixed @ Wp^T + bias + x =====
    #pragma unroll
    for (int mi = 0; mi < 2; mi++)
        #pragma unroll
        for (int ni = 0; ni < 8; ni++)
            #pragma unroll
            for (int k = 0; k < 4; k++) acc[mi][ni][k] = 0.f;
    stage_w(smb, g_wp, 0, 0, tid);
    gemm_phase(smb, g_wp, acc, aB0, aB1, bB, tid);

    // epilogue 2: stage quarter col-blocks -> coalesced float4 out = acc + bias + x
    {
        float* stg = (float*)(sm + SM_B);   // [64][68] fp32 per quarter
        for (int q = 0; q < 4; q++) {
            if ((warp >> 1) == q) {
                #pragma unroll
                for (int mi = 0; mi < 2; mi++)
                    #pragma unroll
                    for (int ni = 0; ni < 8; ni++) {
                        int m = wm + mi * 16 + g;
                        int e = ni * 8 + tg * 2;
                        stg[m * 68 + e]           = acc[mi][ni][0];
                        stg[m * 68 + e + 1]       = acc[mi][ni][1];
                        stg[(m + 8) * 68 + e]     = acc[mi][ni][2];
                        stg[(m + 8) * 68 + e + 1] = acc[mi][ni][3];
                    }
            }
            __syncthreads();
            #pragma unroll
            for (int it = 0; it < 4; it++) {
                int idx = it * 256 + tid;        // 0..1023
                int row = idx >> 4;              // view 0..63
                int c4  = (idx & 15) * 4;        // col in quarter
                size_t gbase = ((size_t)(b * VV + row) * TT + t) * DD + q * 64 + c4;
                float4 s  = *(float4*)(stg + row * 68 + c4);
                float4 xr = *(const float4*)(x + gbase);
                float4 bb = *(const float4*)(b_proj + q * 64 + c4);
                float4 o;
                o.x = s.x + bb.x + xr.x;
                o.y = s.y + bb.y + xr.y;
                o.z = s.z + bb.z + xr.z;
                o.w = s.w + bb.w + xr.w;
                *(float4*)(out + gbase) = o;
            }
            __syncthreads();
        }
    }
}

// ---------------- launch ----------------
extern "C" void kernel_launch(void* const* d_in, const int* in_sizes, int n_in,
                              void* d_out, int out_size) {
    const float* x        = (const float*)d_in[0];
    const void*  obs_mask = d_in[1];
    const float* ln_w     = (const float*)d_in[2];
    const float* ln_b     = (const float*)d_in[3];
    const float* w_qkv    = (const float*)d_in[4];
    const float* w_proj   = (const float*)d_in[5];
    const float* b_proj   = (const float*)d_in[6];
    float* out = (float*)d_out;

    cudaFuncSetAttribute(fused_kernel, cudaFuncAttributeMaxDynamicSharedMemorySize, SMEM_TOT);

    prep_kernel<<<256, 256>>>(w_qkv, w_proj, (const unsigned char*)obs_mask);
    ln_kernel<<<dim3(BB*VV, 8), 256>>>(x, obs_mask, ln_w, ln_b);
    qk_kernel<<<BB*VV, 256>>>(w_qkv);
    attn_kernel<<<BB*HH, 256>>>();
    fused_kernel<<<dim3(TT, BB), 256, SMEM_TOT>>>(x, b_proj, out);
}

// round 11
// speedup vs baseline: 1.7435x; 1.1851x over previous
#include <cuda_runtime.h>
#include <cuda_bf16.h>
#include <stdint.h>

#define BB 8
#define VV 64
#define TT 257
#define DD 256
#define HH 8
#define DH 32

#define XN_ELEMS (BB*VV*TT*DD)

// ---------------- scratch ----------------
__device__ __align__(128) __nv_bfloat16 g_xn[XN_ELEMS];
__device__ __align__(128) float  g_xsum8[8*BB*VV*DD];
__device__ __align__(128) float  g_cnt8[8*BB*VV];
__device__ __align__(128) float  g_q[BB*VV*DD];
__device__ __align__(128) float  g_k[BB*VV*DD];
__device__ __align__(128) __nv_bfloat16 g_attn[BB*HH*VV*VV];
__device__ __align__(128) __nv_bfloat16 g_wv[DD*DD];    // w_qkv rows 512..767 [e][k]
__device__ __align__(128) __nv_bfloat16 g_wp[DD*DD];    // w_proj [e][k]

// ---------------- helpers ----------------
__device__ __forceinline__ uint32_t smem_u32(const void* p) {
    uint32_t a;
    asm("{ .reg .u64 t; cvta.to.shared.u64 t, %1; cvt.u32.u64 %0, t; }" : "=r"(a) : "l"(p));
    return a;
}
__device__ __forceinline__ void mma16816(float* c, const uint32_t* a, uint32_t b0, uint32_t b1) {
    asm volatile(
        "mma.sync.aligned.m16n8k16.row.col.f32.bf16.bf16.f32 "
        "{%0,%1,%2,%3}, {%4,%5,%6,%7}, {%8,%9}, {%0,%1,%2,%3};"
        : "+f"(c[0]), "+f"(c[1]), "+f"(c[2]), "+f"(c[3])
        : "r"(a[0]), "r"(a[1]), "r"(a[2]), "r"(a[3]), "r"(b0), "r"(b1));
}
__device__ __forceinline__ void ldm_x4(uint32_t* r, uint32_t addr) {
    asm volatile("ldmatrix.sync.aligned.m8n8.x4.shared.b16 {%0,%1,%2,%3}, [%4];"
        : "=r"(r[0]), "=r"(r[1]), "=r"(r[2]), "=r"(r[3]) : "r"(addr));
}
__device__ __forceinline__ void cp_async16(uint32_t smem, const void* gmem) {
    asm volatile("cp.async.cg.shared.global [%0], [%1], 16;\n" :: "r"(smem), "l"(gmem));
}
#define CP_COMMIT() asm volatile("cp.async.commit_group;\n" ::: "memory")
#define CP_WAIT1()  asm volatile("cp.async.wait_group 1;\n" ::: "memory")
#define CP_WAIT0()  asm volatile("cp.async.wait_group 0;\n" ::: "memory")

__device__ __forceinline__ bool mask_at(const void* m, int idx, int kind) {
    if (kind == 0) return ((const int*)m)[idx] != 0;
    if (kind == 1) return ((const unsigned char*)m)[idx] != 0;
    return ((const float*)m)[idx] != 0.0f;
}

// ---------------- LayerNorm (warp-per-row, mask-kind detect inline) ----------------
// grid (512, 8): (b*64+v, t-slice of 33). 256 threads = 8 warps.
__global__ void __launch_bounds__(256)
ln_kernel(const float* __restrict__ x, const void* __restrict__ obs_mask,
          const float* __restrict__ ln_w, const float* __restrict__ ln_b) {
    int bv = blockIdx.x;
    int y  = blockIdx.y;
    int t0 = y * 33;
    int t1 = min(TT, t0 + 33);
    int warp = threadIdx.x >> 5, lane = threadIdx.x & 31;

    __shared__ float wsum[8][DD];
    __shared__ float wcnt[8];
    __shared__ int s_kind;

    // mask dtype detection (bool 1B / int32 / float32) — warp 0, ballot-reduced
    if (warp == 0) {
        const unsigned char* m = (const unsigned char*)obs_mask;
        int any = 0, isf = 0;
        for (int j = lane; j < 1024; j += 32) {
            unsigned char b1 = m[j*4+1], b2 = m[j*4+2], b3 = m[j*4+3];
            if (b1 | b2 | b3) any = 1;
            if (b3 == 0x3f) isf = 1;
        }
        unsigned anym = __ballot_sync(0xffffffffu, any);
        unsigned isfm = __ballot_sync(0xffffffffu, isf);
        if (lane == 0) s_kind = isfm ? 2 : (anym ? 1 : 0);
    }
    __syncthreads();
    int kind = s_kind;

    float4 w0  = *(const float4*)(ln_w + lane*4);
    float4 w1  = *(const float4*)(ln_w + 128 + lane*4);
    float4 lb0 = *(const float4*)(ln_b + lane*4);
    float4 lb1 = *(const float4*)(ln_b + 128 + lane*4);

    float acc[8];
    #pragma unroll
    for (int i = 0; i < 8; i++) acc[i] = 0.0f;
    float cnt = 0.0f;

    for (int t = t0 + warp; t < t1; t += 8) {
        size_t base = ((size_t)bv * TT + t) * DD;
        float4 v0 = *(const float4*)(x + base + lane*4);
        float4 v1 = *(const float4*)(x + base + 128 + lane*4);
        float s  = v0.x + v0.y + v0.z + v0.w + v1.x + v1.y + v1.z + v1.w;
        float s2 = v0.x*v0.x + v0.y*v0.y + v0.z*v0.z + v0.w*v0.w
                 + v1.x*v1.x + v1.y*v1.y + v1.z*v1.z + v1.w*v1.w;
        #pragma unroll
        for (int o = 16; o > 0; o >>= 1) {
            s  += __shfl_xor_sync(0xffffffffu, s, o);
            s2 += __shfl_xor_sync(0xffffffffu, s2, o);
        }
        float mu  = s * (1.0f/256.0f);
        float var = s2 * (1.0f/256.0f) - mu * mu;
        float rstd = rsqrtf(var + 1e-5f);

        float xn[8];
        xn[0] = (v0.x - mu) * rstd * w0.x + lb0.x;
        xn[1] = (v0.y - mu) * rstd * w0.y + lb0.y;
        xn[2] = (v0.z - mu) * rstd * w0.z + lb0.z;
        xn[3] = (v0.w - mu) * rstd * w0.w + lb0.w;
        xn[4] = (v1.x - mu) * rstd * w1.x + lb1.x;
        xn[5] = (v1.y - mu) * rstd * w1.y + lb1.y;
        xn[6] = (v1.z - mu) * rstd * w1.z + lb1.z;
        xn[7] = (v1.w - mu) * rstd * w1.w + lb1.w;

        __nv_bfloat162 p0 = __floats2bfloat162_rn(xn[0], xn[1]);
        __nv_bfloat162 p1 = __floats2bfloat162_rn(xn[2], xn[3]);
        __nv_bfloat162 p2 = __floats2bfloat162_rn(xn[4], xn[5]);
        __nv_bfloat162 p3 = __floats2bfloat162_rn(xn[6], xn[7]);
        uint2 u0; u0.x = *(uint32_t*)&p0; u0.y = *(uint32_t*)&p1;
        uint2 u1; u1.x = *(uint32_t*)&p2; u1.y = *(uint32_t*)&p3;
        *(uint2*)(g_xn + base + lane*4)       = u0;
        *(uint2*)(g_xn + base + 128 + lane*4) = u1;

        bool mk = (t == 0) || mask_at(obs_mask, bv * (TT-1) + (t - 1), kind);
        if (mk) {
            #pragma unroll
            for (int i = 0; i < 8; i++) acc[i] += xn[i];
            cnt += 1.0f;
        }
    }
    #pragma unroll
    for (int i = 0; i < 4; i++) {
        wsum[warp][lane*4 + i]       = acc[i];
        wsum[warp][128 + lane*4 + i] = acc[4 + i];
    }
    if (lane == 0) wcnt[warp] = cnt;
    __syncthreads();
    int tid = threadIdx.x;
    float S = 0.f;
    #pragma unroll
    for (int wv = 0; wv < 8; wv++) S += wsum[wv][tid];
    g_xsum8[(y * BB*VV + bv) * DD + tid] = S;
    if (tid == 0) {
        float C = 0.f;
        #pragma unroll
        for (int wv = 0; wv < 8; wv++) C += wcnt[wv];
        g_cnt8[y * BB*VV + bv] = C;
    }
}

// ---------------- q / k projections + weight bf16 conversion ----------------
__global__ void qkw_kernel(const float* __restrict__ w_qkv, const float* __restrict__ w_proj) {
    int bv = blockIdx.x;
    int tid = threadIdx.x;
    // weight conversion: blocks 0..255 cover all 65536 elements of each matrix
    {
        int i = blockIdx.x * 256 + tid;
        if (i < DD*DD) {
            g_wv[i] = __float2bfloat16(w_qkv[2*DD*DD + i]);
            g_wp[i] = __float2bfloat16(w_proj[i]);
        }
    }
    __shared__ float xn0[DD], xm[DD];
    xn0[tid] = __bfloat162float(g_xn[(size_t)bv * TT * DD + tid]);
    {
        float S = 0.f, C = 0.f;
        #pragma unroll
        for (int y = 0; y < 8; y++) {
            S += g_xsum8[(y * BB*VV + bv) * DD + tid];
            C += g_cnt8[y * BB*VV + bv];
        }
        xm[tid] = S / C;
    }
    __syncthreads();
    int warp = tid >> 5, lane = tid & 31;
    for (int e = warp; e < DD; e += 8) {
        const float4* wq = (const float4*)(w_qkv + (size_t)e * DD);
        const float4* wk = (const float4*)(w_qkv + (size_t)(DD + e) * DD);
        float q = 0.f, k = 0.f;
        #pragma unroll
        for (int i = lane; i < 64; i += 32) {
            float4 aq = wq[i], ak = wk[i];
            const float* xq = xn0 + i * 4;
            const float* xk = xm + i * 4;
            q += xq[0]*aq.x + xq[1]*aq.y + xq[2]*aq.z + xq[3]*aq.w;
            k += xk[0]*ak.x + xk[1]*ak.y + xk[2]*ak.z + xk[3]*ak.w;
        }
        #pragma unroll
        for (int o = 16; o > 0; o >>= 1) {
            q += __shfl_xor_sync(0xffffffffu, q, o);
            k += __shfl_xor_sync(0xffffffffu, k, o);
        }
        if (lane == 0) { g_q[bv * DD + e] = q; g_k[bv * DD + e] = k; }
    }
}

// ---------------- attention softmax ----------------
__global__ void attn_kernel() {
    int b = blockIdx.x >> 3, h = blockIdx.x & 7;
    __shared__ float qs[VV][33], ks[VV][33];
    __shared__ float lg[VV][65];
    int tid = threadIdx.x;
    for (int i = tid; i < VV * DH; i += 256) {
        int v = i >> 5, dd = i & 31;
        qs[v][dd] = g_q[(b * VV + v) * DD + h * DH + dd];
        ks[v][dd] = g_k[(b * VV + v) * DD + h * DH + dd];
    }
    __syncthreads();
    const float scale = 0.17677669529663687f;
    for (int p = tid; p < VV * VV; p += 256) {
        int i = p >> 6, j = p & 63;
        float s = 0.f;
        #pragma unroll
        for (int c = 0; c < DH; c++) s += qs[i][c] * ks[j][c];
        lg[i][j] = s * scale;
    }
    __syncthreads();
    int warp = tid >> 5, lane = tid & 31;
    for (int r = warp; r < VV; r += 8) {
        float v0 = lg[r][lane], v1 = lg[r][lane + 32];
        float m = fmaxf(v0, v1);
        #pragma unroll
        for (int o = 16; o > 0; o >>= 1) m = fmaxf(m, __shfl_xor_sync(0xffffffffu, m, o));
        float e0 = __expf(v0 - m), e1 = __expf(v1 - m);
        float s = e0 + e1;
        #pragma unroll
        for (int o = 16; o > 0; o >>= 1) s += __shfl_xor_sync(0xffffffffu, s, o);
        float inv = 1.0f / s;
        __nv_bfloat16* ap = g_attn + ((size_t)(b * HH + h) * VV + r) * VV;
        ap[lane]      = __float2bfloat16(e0 * inv);
        ap[lane + 32] = __float2bfloat16(e1 * inv);
    }
}

// ---------------- fused: M=128 (two t's), 512 threads, 1 CTA/SM ----------------
// grid (129, 8). smem:
//   A   [128][XS=264] bf16 @ 0       (67584 B)  xn, then mixed
//   B   2 x [256][BS2=72] bf16 @ SM_B (73728 B) weight k-chunks of 64; fp32 out-stage
//   vfT [256][VSTR=136] bf16 @ SM_VFT (69632 B)
#define XS 264
#define BS2 72
#define VSTR 136
#define SM_A 0
#define SM_B 67584
#define BBUF 36864
#define SM_VFT 141312
#define SMEM_TOT 210944

__device__ __forceinline__ void stage_w(uint32_t smb, const __nv_bfloat16* W, int kc, int buf, int tid) {
    int e = tid >> 1, half = tid & 1;
    uint32_t dst = smb + SM_B + buf * BBUF + (uint32_t)(e * (BS2*2) + half * 64);
    const __nv_bfloat16* src = W + e * DD + kc * 64 + half * 32;
    #pragma unroll
    for (int j = 0; j < 4; j++) cp_async16(dst + j * 16, src + j * 8);
    CP_COMMIT();
}

// 128x256x256 GEMM: acc += A(smem) @ W^T ; chunk0 staged+committed by caller
__device__ __forceinline__ void gemm_phase(uint32_t smb, const __nv_bfloat16* __restrict__ W,
                                           float acc[2][8][4],
                                           const uint32_t aB0, const uint32_t aB1,
                                           const uint32_t* bB, int tid) {
    for (int kc = 0; kc < 4; kc++) {
        if (kc < 3) { stage_w(smb, W, kc + 1, (kc + 1) & 1, tid); CP_WAIT1(); }
        else        { CP_WAIT0(); }
        __syncthreads();
        uint32_t bufo = (uint32_t)((kc & 1) * BBUF);
        #pragma unroll
        for (int ks = 0; ks < 4; ks++) {
            uint32_t kbyte = (uint32_t)((kc * 64 + ks * 16) * 2);
            uint32_t a[2][4];
            ldm_x4(a[0], aB0 + kbyte);
            ldm_x4(a[1], aB1 + kbyte);
            #pragma unroll
            for (int p = 0; p < 4; p++) {
                uint32_t bf[4];
                ldm_x4(bf, bB[p] + bufo + (uint32_t)(ks * 32));
                mma16816(acc[0][2*p],   a[0], bf[0], bf[1]);
                mma16816(acc[1][2*p],   a[1], bf[0], bf[1]);
                mma16816(acc[0][2*p+1], a[0], bf[2], bf[3]);
                mma16816(acc[1][2*p+1], a[1], bf[2], bf[3]);
            }
        }
        __syncthreads();
    }
}

__global__ void __launch_bounds__(512, 1)
fused_kernel(const float* __restrict__ x, const float* __restrict__ b_proj,
             float* __restrict__ out) {
    const int tile = blockIdx.x;            // t-pair: t = 2*tile + {0,1}
    const int b    = blockIdx.y;
    extern __shared__ __align__(128) char sm[];
    const uint32_t smb = smem_u32(sm);
    __nv_bfloat16* xn_s = (__nv_bfloat16*)(sm + SM_A);
    __nv_bfloat16* vf_t = (__nv_bfloat16*)(sm + SM_VFT);

    const int tid  = threadIdx.x;
    const int warp = tid >> 5, lane = tid & 31;
    const int g = lane >> 2, tg = lane & 3;
    const int wm = (warp & 3) * 32;
    const int wn = (warp >> 2) * 64;

    // ldmatrix base addresses
    const int sel = lane >> 3;
    uint32_t aB0, aB1, bB[4];
    {
        int arow = wm + (sel & 1) * 8 + (lane & 7);
        uint32_t abase = smb + SM_A + (uint32_t)((arow * XS + (sel >> 1) * 8) * 2);
        aB0 = abase;
        aB1 = abase + (uint32_t)(16 * XS * 2);
        int n_off = (lane >> 4) * 8 + (lane & 7);
        int kb = ((lane >> 3) & 1) * 8;
        #pragma unroll
        for (int p = 0; p < 4; p++)
            bB[p] = smb + SM_B + (uint32_t)(((wn + p * 16 + n_off) * BS2 + kb) * 2);
    }

    // stage A (128 rows of xn) then W chunk 0
    {
        #pragma unroll
        for (int it = 0; it < 8; it++) {
            int idx = it * 512 + tid;            // 0..4095
            int row = idx >> 5, c16 = idx & 31;
            int tl = row >> 6, v = row & 63;
            int tglob = min(2 * tile + tl, 256);
            uint32_t dst = smb + SM_A + (uint32_t)(row * XS * 2 + c16 * 16);
            const void* src = g_xn + ((size_t)(b * VV + v) * TT + tglob) * DD + c16 * 8;
            cp_async16(dst, src);
        }
        CP_COMMIT();
    }
    stage_w(smb, g_wv, 0, 0, tid);

    // ===== Phase 0: vf = xn @ Wv^T =====
    float acc[2][8][4];
    #pragma unroll
    for (int mi = 0; mi < 2; mi++)
        #pragma unroll
        for (int ni = 0; ni < 8; ni++)
            #pragma unroll
            for (int k = 0; k < 4; k++) acc[mi][ni][k] = 0.f;
    gemm_phase(smb, g_wv, acc, aB0, aB1, bB, tid);

    // prefetch Wp chunk 0 into buf 0 (overlaps epilogue + mix)
    stage_w(smb, g_wp, 0, 0, tid);

    // epilogue 0: acc -> vfT[e][m]
    #pragma unroll
    for (int mi = 0; mi < 2; mi++)
        #pragma unroll
        for (int ni = 0; ni < 8; ni++) {
            int m = wm + mi * 16 + g;
            int e = wn + ni * 8 + tg * 2;
            vf_t[(e    ) * VSTR + m    ] = __float2bfloat16(acc[mi][ni][0]);
            vf_t[(e + 1) * VSTR + m    ] = __float2bfloat16(acc[mi][ni][1]);
            vf_t[(e    ) * VSTR + m + 8] = __float2bfloat16(acc[mi][ni][2]);
            vf_t[(e + 1) * VSTR + m + 8] = __float2bfloat16(acc[mi][ni][3]);
        }
    __syncthreads();

    // ===== Mix: warp w -> head h = w&7, t-half tl = w>>3 ; 64x32x64 =====
    {
        const int h = warp & 7, tl = warp >> 3;
        float macc[4][4][4];
        #pragma unroll
        for (int mi = 0; mi < 4; mi++)
            #pragma unroll
            for (int ni = 0; ni < 4; ni++)
                #pragma unroll
                for (int k = 0; k < 4; k++) macc[mi][ni][k] = 0.f;

        const __nv_bfloat16* attn_p = g_attn + (size_t)(b * HH + h) * VV * VV;
        #pragma unroll
        for (int ks = 0; ks < 4; ks++) {
            int kk = ks * 16;
            uint32_t a[4][4];
            #pragma unroll
            for (int mi = 0; mi < 4; mi++) {
                const __nv_bfloat16* ap = attn_p + (mi*16 + g) * VV + kk + tg*2;
                a[mi][0] = *(const uint32_t*)(ap);
                a[mi][1] = *(const uint32_t*)(ap + 8 * VV);
                a[mi][2] = *(const uint32_t*)(ap + 8);
                a[mi][3] = *(const uint32_t*)(ap + 8 * VV + 8);
            }
            #pragma unroll
            for (int ni = 0; ni < 4; ni++) {
                const __nv_bfloat16* bp = vf_t + (h * DH + ni*8 + g) * VSTR + tl * 64 + kk + tg*2;
                uint32_t b0 = *(const uint32_t*)(bp);
                uint32_t b1 = *(const uint32_t*)(bp + 8);
                #pragma unroll
                for (int mi = 0; mi < 4; mi++) mma16816(macc[mi][ni], a[mi], b0, b1);
            }
        }
        __syncthreads();   // reads of xn_s/vf_t done before aliasing write into A
        #pragma unroll
        for (int mi = 0; mi < 4; mi++)
            #pragma unroll
            for (int ni = 0; ni < 4; ni++) {
                int m = tl * 64 + mi*16 + g;
                int n = h * DH + ni*8 + tg*2;
                __nv_bfloat162 p01 = __floats2bfloat162_rn(macc[mi][ni][0], macc[mi][ni][1]);
                __nv_bfloat162 p23 = __floats2bfloat162_rn(macc[mi][ni][2], macc[mi][ni][3]);
                *(__nv_bfloat162*)(xn_s + m * XS + n)       = p01;
                *(__nv_bfloat162*)(xn_s + (m + 8) * XS + n) = p23;
            }
    }
    __syncthreads();

    // ===== Phase 2: out = mixed @ Wp^T + bias + x =====
    #pragma unroll
    for (int mi = 0; mi < 2; mi++)
        #pragma unroll
        for (int ni = 0; ni < 8; ni++)
            #pragma unroll
            for (int k = 0; k < 4; k++) acc[mi][ni][k] = 0.f;
    gemm_phase(smb, g_wp, acc, aB0, aB1, bB, tid);

    // epilogue 2: per col-quarter, stage fp32 -> coalesced float4 out
    {
        float* stg = (float*)(sm + SM_B);   // [128][68] fp32
        for (int q = 0; q < 4; q++) {
            if ((warp >> 2) == q) {
                #pragma unroll
                for (int mi = 0; mi < 2; mi++)
                    #pragma unroll
                    for (int ni = 0; ni < 8; ni++) {
                        int m = wm + mi * 16 + g;
                        int e = ni * 8 + tg * 2;
                        stg[m * 68 + e]           = acc[mi][ni][0];
                        stg[m * 68 + e + 1]       = acc[mi][ni][1];
                        stg[(m + 8) * 68 + e]     = acc[mi][ni][2];
                        stg[(m + 8) * 68 + e + 1] = acc[mi][ni][3];
                    }
            }
            __syncthreads();
            #pragma unroll
            for (int it = 0; it < 4; it++) {
                int idx = it * 512 + tid;        // 0..2047
                int row = idx >> 4;              // 0..127
                int c4  = (idx & 15) * 4;
                int tl = row >> 6, v = row & 63;
                int tglob = 2 * tile + tl;
                if (tglob <= 256) {
                    size_t gbase = ((size_t)(b * VV + v) * TT + tglob) * DD + q * 64 + c4;
                    float4 s  = *(float4*)(stg + row * 68 + c4);
                    float4 xr = *(const float4*)(x + gbase);
                    float4 bb = *(const float4*)(b_proj + q * 64 + c4);
                    float4 o;
                    o.x = s.x + bb.x + xr.x;
                    o.y = s.y + bb.y + xr.y;
                    o.z = s.z + bb.z + xr.z;
                    o.w = s.w + bb.w + xr.w;
                    *(float4*)(out + gbase) = o;
                }
            }
            __syncthreads();
        }
    }
}

// ---------------- launch: 4 kernels, fused at index 3 (profiled) ----------------
extern "C" void kernel_launch(void* const* d_in, const int* in_sizes, int n_in,
                              void* d_out, int out_size) {
    const float* x        = (const float*)d_in[0];
    const void*  obs_mask = d_in[1];
    const float* ln_w     = (const float*)d_in[2];
    const float* ln_b     = (const float*)d_in[3];
    const float* w_qkv    = (const float*)d_in[4];
    const float* w_proj   = (const float*)d_in[5];
    const float* b_proj   = (const float*)d_in[6];
    float* out = (float*)d_out;

    cudaFuncSetAttribute(fused_kernel, cudaFuncAttributeMaxDynamicSharedMemorySize, SMEM_TOT);

    ln_kernel<<<dim3(BB*VV, 8), 256>>>(x, obs_mask, ln_w, ln_b);
    qkw_kernel<<<BB*VV, 256>>>(w_qkv, w_proj);
    attn_kernel<<<BB*HH, 256>>>();
    fused_kernel<<<dim3(129, BB), 512, SMEM_TOT>>>(x, b_proj, out);
}

// round 12
// speedup vs baseline: 1.7665x; 1.0132x over previous
#include <cuda_runtime.h>
#include <cuda_bf16.h>
#include <stdint.h>

#define BB 8
#define VV 64
#define TT 257
#define DD 256
#define HH 8
#define DH 32

#define XN_ELEMS (BB*VV*TT*DD)

// ---------------- scratch ----------------
__device__ __align__(128) __nv_bfloat16 g_xn[XN_ELEMS];
__device__ __align__(128) float  g_xsum8[8*BB*VV*DD];
__device__ __align__(128) float  g_cnt8[8*BB*VV];
__device__ __align__(128) float  g_q[BB*VV*DD];
__device__ __align__(128) float  g_k[BB*VV*DD];
__device__ __align__(128) __nv_bfloat16 g_attn[BB*HH*VV*VV];
__device__ __align__(128) __nv_bfloat16 g_wv[DD*DD];    // w_qkv rows 512..767 [e][k]
__device__ __align__(128) __nv_bfloat16 g_wp[DD*DD];    // w_proj [e][k]

// ---------------- helpers ----------------
__device__ __forceinline__ uint32_t smem_u32(const void* p) {
    uint32_t a;
    asm("{ .reg .u64 t; cvta.to.shared.u64 t, %1; cvt.u32.u64 %0, t; }" : "=r"(a) : "l"(p));
    return a;
}
__device__ __forceinline__ void mma16816(float* c, const uint32_t* a, uint32_t b0, uint32_t b1) {
    asm volatile(
        "mma.sync.aligned.m16n8k16.row.col.f32.bf16.bf16.f32 "
        "{%0,%1,%2,%3}, {%4,%5,%6,%7}, {%8,%9}, {%0,%1,%2,%3};"
        : "+f"(c[0]), "+f"(c[1]), "+f"(c[2]), "+f"(c[3])
        : "r"(a[0]), "r"(a[1]), "r"(a[2]), "r"(a[3]), "r"(b0), "r"(b1));
}
__device__ __forceinline__ void ldm_x4(uint32_t* r, uint32_t addr) {
    asm volatile("ldmatrix.sync.aligned.m8n8.x4.shared.b16 {%0,%1,%2,%3}, [%4];"
        : "=r"(r[0]), "=r"(r[1]), "=r"(r[2]), "=r"(r[3]) : "r"(addr));
}
__device__ __forceinline__ void cp_async16(uint32_t smem, const void* gmem) {
    asm volatile("cp.async.cg.shared.global [%0], [%1], 16;\n" :: "r"(smem), "l"(gmem));
}
#define CP_COMMIT() asm volatile("cp.async.commit_group;\n" ::: "memory")
#define CP_WAIT0()  asm volatile("cp.async.wait_group 0;\n" ::: "memory")

__device__ __forceinline__ bool mask_at(const void* m, int idx, int kind) {
    if (kind == 0) return ((const int*)m)[idx] != 0;
    if (kind == 1) return ((const unsigned char*)m)[idx] != 0;
    return ((const float*)m)[idx] != 0.0f;
}

// ---------------- LayerNorm (warp-per-row, mask-kind detect inline) ----------------
__global__ void __launch_bounds__(256)
ln_kernel(const float* __restrict__ x, const void* __restrict__ obs_mask,
          const float* __restrict__ ln_w, const float* __restrict__ ln_b) {
    int bv = blockIdx.x;
    int y  = blockIdx.y;
    int t0 = y * 33;
    int t1 = min(TT, t0 + 33);
    int warp = threadIdx.x >> 5, lane = threadIdx.x & 31;

    __shared__ float wsum[8][DD];
    __shared__ float wcnt[8];
    __shared__ int s_kind;

    if (warp == 0) {
        const unsigned char* m = (const unsigned char*)obs_mask;
        int any = 0, isf = 0;
        for (int j = lane; j < 1024; j += 32) {
            unsigned char b1 = m[j*4+1], b2 = m[j*4+2], b3 = m[j*4+3];
            if (b1 | b2 | b3) any = 1;
            if (b3 == 0x3f) isf = 1;
        }
        unsigned anym = __ballot_sync(0xffffffffu, any);
        unsigned isfm = __ballot_sync(0xffffffffu, isf);
        if (lane == 0) s_kind = isfm ? 2 : (anym ? 1 : 0);
    }
    __syncthreads();
    int kind = s_kind;

    float4 w0  = *(const float4*)(ln_w + lane*4);
    float4 w1  = *(const float4*)(ln_w + 128 + lane*4);
    float4 lb0 = *(const float4*)(ln_b + lane*4);
    float4 lb1 = *(const float4*)(ln_b + 128 + lane*4);

    float acc[8];
    #pragma unroll
    for (int i = 0; i < 8; i++) acc[i] = 0.0f;
    float cnt = 0.0f;

    for (int t = t0 + warp; t < t1; t += 8) {
        size_t base = ((size_t)bv * TT + t) * DD;
        float4 v0 = *(const float4*)(x + base + lane*4);
        float4 v1 = *(const float4*)(x + base + 128 + lane*4);
        float s  = v0.x + v0.y + v0.z + v0.w + v1.x + v1.y + v1.z + v1.w;
        float s2 = v0.x*v0.x + v0.y*v0.y + v0.z*v0.z + v0.w*v0.w
                 + v1.x*v1.x + v1.y*v1.y + v1.z*v1.z + v1.w*v1.w;
        #pragma unroll
        for (int o = 16; o > 0; o >>= 1) {
            s  += __shfl_xor_sync(0xffffffffu, s, o);
            s2 += __shfl_xor_sync(0xffffffffu, s2, o);
        }
        float mu  = s * (1.0f/256.0f);
        float var = s2 * (1.0f/256.0f) - mu * mu;
        float rstd = rsqrtf(var + 1e-5f);

        float xn[8];
        xn[0] = (v0.x - mu) * rstd * w0.x + lb0.x;
        xn[1] = (v0.y - mu) * rstd * w0.y + lb0.y;
        xn[2] = (v0.z - mu) * rstd * w0.z + lb0.z;
        xn[3] = (v0.w - mu) * rstd * w0.w + lb0.w;
        xn[4] = (v1.x - mu) * rstd * w1.x + lb1.x;
        xn[5] = (v1.y - mu) * rstd * w1.y + lb1.y;
        xn[6] = (v1.z - mu) * rstd * w1.z + lb1.z;
        xn[7] = (v1.w - mu) * rstd * w1.w + lb1.w;

        __nv_bfloat162 p0 = __floats2bfloat162_rn(xn[0], xn[1]);
        __nv_bfloat162 p1 = __floats2bfloat162_rn(xn[2], xn[3]);
        __nv_bfloat162 p2 = __floats2bfloat162_rn(xn[4], xn[5]);
        __nv_bfloat162 p3 = __floats2bfloat162_rn(xn[6], xn[7]);
        uint2 u0; u0.x = *(uint32_t*)&p0; u0.y = *(uint32_t*)&p1;
        uint2 u1; u1.x = *(uint32_t*)&p2; u1.y = *(uint32_t*)&p3;
        *(uint2*)(g_xn + base + lane*4)       = u0;
        *(uint2*)(g_xn + base + 128 + lane*4) = u1;

        bool mk = (t == 0) || mask_at(obs_mask, bv * (TT-1) + (t - 1), kind);
        if (mk) {
            #pragma unroll
            for (int i = 0; i < 8; i++) acc[i] += xn[i];
            cnt += 1.0f;
        }
    }
    #pragma unroll
    for (int i = 0; i < 4; i++) {
        wsum[warp][lane*4 + i]       = acc[i];
        wsum[warp][128 + lane*4 + i] = acc[4 + i];
    }
    if (lane == 0) wcnt[warp] = cnt;
    __syncthreads();
    int tid = threadIdx.x;
    float S = 0.f;
    #pragma unroll
    for (int wv = 0; wv < 8; wv++) S += wsum[wv][tid];
    g_xsum8[(y * BB*VV + bv) * DD + tid] = S;
    if (tid == 0) {
        float C = 0.f;
        #pragma unroll
        for (int wv = 0; wv < 8; wv++) C += wcnt[wv];
        g_cnt8[y * BB*VV + bv] = C;
    }
}

// ---------------- q / k projections + weight bf16 conversion ----------------
__global__ void qkw_kernel(const float* __restrict__ w_qkv, const float* __restrict__ w_proj) {
    int bv = blockIdx.x;
    int tid = threadIdx.x;
    {
        int i = blockIdx.x * 256 + tid;
        if (i < DD*DD) {
            g_wv[i] = __float2bfloat16(w_qkv[2*DD*DD + i]);
            g_wp[i] = __float2bfloat16(w_proj[i]);
        }
    }
    __shared__ float xn0[DD], xm[DD];
    xn0[tid] = __bfloat162float(g_xn[(size_t)bv * TT * DD + tid]);
    {
        float S = 0.f, C = 0.f;
        #pragma unroll
        for (int y = 0; y < 8; y++) {
            S += g_xsum8[(y * BB*VV + bv) * DD + tid];
            C += g_cnt8[y * BB*VV + bv];
        }
        xm[tid] = S / C;
    }
    __syncthreads();
    int warp = tid >> 5, lane = tid & 31;
    for (int e = warp; e < DD; e += 8) {
        const float4* wq = (const float4*)(w_qkv + (size_t)e * DD);
        const float4* wk = (const float4*)(w_qkv + (size_t)(DD + e) * DD);
        float q = 0.f, k = 0.f;
        #pragma unroll
        for (int i = lane; i < 64; i += 32) {
            float4 aq = wq[i], ak = wk[i];
            const float* xq = xn0 + i * 4;
            const float* xk = xm + i * 4;
            q += xq[0]*aq.x + xq[1]*aq.y + xq[2]*aq.z + xq[3]*aq.w;
            k += xk[0]*ak.x + xk[1]*ak.y + xk[2]*ak.z + xk[3]*ak.w;
        }
        #pragma unroll
        for (int o = 16; o > 0; o >>= 1) {
            q += __shfl_xor_sync(0xffffffffu, q, o);
            k += __shfl_xor_sync(0xffffffffu, k, o);
        }
        if (lane == 0) { g_q[bv * DD + e] = q; g_k[bv * DD + e] = k; }
    }
}

// ---------------- attention softmax ----------------
__global__ void attn_kernel() {
    int b = blockIdx.x >> 3, h = blockIdx.x & 7;
    __shared__ float qs[VV][33], ks[VV][33];
    __shared__ float lg[VV][65];
    int tid = threadIdx.x;
    for (int i = tid; i < VV * DH; i += 256) {
        int v = i >> 5, dd = i & 31;
        qs[v][dd] = g_q[(b * VV + v) * DD + h * DH + dd];
        ks[v][dd] = g_k[(b * VV + v) * DD + h * DH + dd];
    }
    __syncthreads();
    const float scale = 0.17677669529663687f;
    for (int p = tid; p < VV * VV; p += 256) {
        int i = p >> 6, j = p & 63;
        float s = 0.f;
        #pragma unroll
        for (int c = 0; c < DH; c++) s += qs[i][c] * ks[j][c];
        lg[i][j] = s * scale;
    }
    __syncthreads();
    int warp = tid >> 5, lane = tid & 31;
    for (int r = warp; r < VV; r += 8) {
        float v0 = lg[r][lane], v1 = lg[r][lane + 32];
        float m = fmaxf(v0, v1);
        #pragma unroll
        for (int o = 16; o > 0; o >>= 1) m = fmaxf(m, __shfl_xor_sync(0xffffffffu, m, o));
        float e0 = __expf(v0 - m), e1 = __expf(v1 - m);
        float s = e0 + e1;
        #pragma unroll
        for (int o = 16; o > 0; o >>= 1) s += __shfl_xor_sync(0xffffffffu, s, o);
        float inv = 1.0f / s;
        __nv_bfloat16* ap = g_attn + ((size_t)(b * HH + h) * VV + r) * VV;
        ap[lane]      = __float2bfloat16(e0 * inv);
        ap[lane + 32] = __float2bfloat16(e1 * inv);
    }
}

// ---------------- fused: M=128 (two t's), 512 threads, 1 CTA/SM ----------------
#define XS 264
#define BS2 72
#define VSTR 136
#define SM_A 0
#define SM_B 67584
#define BBUF 36864
#define SM_VFT 141312
#define SMEM_TOT 210944

__device__ __forceinline__ void stage_w(uint32_t smb, const __nv_bfloat16* W, int kc, int buf, int tid) {
    int e = tid >> 1, half = tid & 1;
    uint32_t dst = smb + SM_B + buf * BBUF + (uint32_t)(e * (BS2*2) + half * 64);
    const __nv_bfloat16* src = W + e * DD + kc * 64 + half * 32;
    #pragma unroll
    for (int j = 0; j < 4; j++) cp_async16(dst + j * 16, src + j * 8);
    CP_COMMIT();
}

// 128x256x256 GEMM: acc += A(smem) @ W^T
// chunk0 staged+committed by caller. One __syncthreads per chunk; staging of
// kc+1 happens after the sync (buffer last read in kc-1, retired before sync).
__device__ __forceinline__ void gemm_phase(uint32_t smb, const __nv_bfloat16* __restrict__ W,
                                           float acc[2][8][4],
                                           const uint32_t aB0, const uint32_t aB1,
                                           const uint32_t* bB, int tid) {
    for (int kc = 0; kc < 4; kc++) {
        CP_WAIT0();
        __syncthreads();
        if (kc < 3) stage_w(smb, W, kc + 1, (kc + 1) & 1, tid);
        uint32_t bufo = (uint32_t)((kc & 1) * BBUF);
        #pragma unroll
        for (int ks = 0; ks < 4; ks++) {
            uint32_t kbyte = (uint32_t)((kc * 64 + ks * 16) * 2);
            // batch ALL fragment loads before any mma: latency exposed once per kstep
            uint32_t a0[4], a1[4], bf[4][4];
            ldm_x4(a0, aB0 + kbyte);
            ldm_x4(a1, aB1 + kbyte);
            #pragma unroll
            for (int p = 0; p < 4; p++)
                ldm_x4(bf[p], bB[p] + bufo + (uint32_t)(ks * 32));
            #pragma unroll
            for (int p = 0; p < 4; p++) {
                mma16816(acc[0][2*p],   a0, bf[p][0], bf[p][1]);
                mma16816(acc[1][2*p],   a1, bf[p][0], bf[p][1]);
                mma16816(acc[0][2*p+1], a0, bf[p][2], bf[p][3]);
                mma16816(acc[1][2*p+1], a1, bf[p][2], bf[p][3]);
            }
        }
    }
}

__global__ void __launch_bounds__(512, 1)
fused_kernel(const float* __restrict__ x, const float* __restrict__ b_proj,
             float* __restrict__ out) {
    const int tile = blockIdx.x;            // t-pair: t = 2*tile + {0,1}
    const int b    = blockIdx.y;
    extern __shared__ __align__(128) char sm[];
    const uint32_t smb = smem_u32(sm);
    __nv_bfloat16* xn_s = (__nv_bfloat16*)(sm + SM_A);
    __nv_bfloat16* vf_t = (__nv_bfloat16*)(sm + SM_VFT);

    const int tid  = threadIdx.x;
    const int warp = tid >> 5, lane = tid & 31;
    const int g = lane >> 2, tg = lane & 3;
    const int wm = (warp & 3) * 32;
    const int wn = (warp >> 2) * 64;

    // ldmatrix base addresses
    const int sel = lane >> 3;
    uint32_t aB0, aB1, bB[4];
    {
        int arow = wm + (sel & 1) * 8 + (lane & 7);
        uint32_t abase = smb + SM_A + (uint32_t)((arow * XS + (sel >> 1) * 8) * 2);
        aB0 = abase;
        aB1 = abase + (uint32_t)(16 * XS * 2);
        int n_off = (lane >> 4) * 8 + (lane & 7);
        int kb = ((lane >> 3) & 1) * 8;
        #pragma unroll
        for (int p = 0; p < 4; p++)
            bB[p] = smb + SM_B + (uint32_t)(((wn + p * 16 + n_off) * BS2 + kb) * 2);
    }

    // stage A (128 rows of xn) then W chunk 0
    {
        #pragma unroll
        for (int it = 0; it < 8; it++) {
            int idx = it * 512 + tid;            // 0..4095
            int row = idx >> 5, c16 = idx & 31;
            int tl = row >> 6, v = row & 63;
            int tglob = min(2 * tile + tl, 256);
            uint32_t dst = smb + SM_A + (uint32_t)(row * XS * 2 + c16 * 16);
            const void* src = g_xn + ((size_t)(b * VV + v) * TT + tglob) * DD + c16 * 8;
            cp_async16(dst, src);
        }
        CP_COMMIT();
    }
    stage_w(smb, g_wv, 0, 0, tid);

    // ===== Phase 0: vf = xn @ Wv^T =====
    float acc[2][8][4];
    #pragma unroll
    for (int mi = 0; mi < 2; mi++)
        #pragma unroll
        for (int ni = 0; ni < 8; ni++)
            #pragma unroll
            for (int k = 0; k < 4; k++) acc[mi][ni][k] = 0.f;
    gemm_phase(smb, g_wv, acc, aB0, aB1, bB, tid);

    // prefetch Wp chunk 0 into buf 0 (overlaps epilogue + mix; buf0 retired in kc=2)
    stage_w(smb, g_wp, 0, 0, tid);

    // epilogue 0: acc -> vfT[e][m]
    #pragma unroll
    for (int mi = 0; mi < 2; mi++)
        #pragma unroll
        for (int ni = 0; ni < 8; ni++) {
            int m = wm + mi * 16 + g;
            int e = wn + ni * 8 + tg * 2;
            vf_t[(e    ) * VSTR + m    ] = __float2bfloat16(acc[mi][ni][0]);
            vf_t[(e + 1) * VSTR + m    ] = __float2bfloat16(acc[mi][ni][1]);
            vf_t[(e    ) * VSTR + m + 8] = __float2bfloat16(acc[mi][ni][2]);
            vf_t[(e + 1) * VSTR + m + 8] = __float2bfloat16(acc[mi][ni][3]);
        }
    __syncthreads();

    // ===== Mix: warp w -> head h = w&7, t-half tl = w>>3 ; 64x32x64 =====
    {
        const int h = warp & 7, tl = warp >> 3;
        float macc[4][4][4];
        #pragma unroll
        for (int mi = 0; mi < 4; mi++)
            #pragma unroll
            for (int ni = 0; ni < 4; ni++)
                #pragma unroll
                for (int k = 0; k < 4; k++) macc[mi][ni][k] = 0.f;

        const __nv_bfloat16* attn_p = g_attn + (size_t)(b * HH + h) * VV * VV;
        #pragma unroll
        for (int ks = 0; ks < 4; ks++) {
            int kk = ks * 16;
            uint32_t a[4][4];
            #pragma unroll
            for (int mi = 0; mi < 4; mi++) {
                const __nv_bfloat16* ap = attn_p + (mi*16 + g) * VV + kk + tg*2;
                a[mi][0] = *(const uint32_t*)(ap);
                a[mi][1] = *(const uint32_t*)(ap + 8 * VV);
                a[mi][2] = *(const uint32_t*)(ap + 8);
                a[mi][3] = *(const uint32_t*)(ap + 8 * VV + 8);
            }
            #pragma unroll
            for (int ni = 0; ni < 4; ni++) {
                const __nv_bfloat16* bp = vf_t + (h * DH + ni*8 + g) * VSTR + tl * 64 + kk + tg*2;
                uint32_t b0 = *(const uint32_t*)(bp);
                uint32_t b1 = *(const uint32_t*)(bp + 8);
                #pragma unroll
                for (int mi = 0; mi < 4; mi++) mma16816(macc[mi][ni], a[mi], b0, b1);
            }
        }
        __syncthreads();   // reads of xn_s/vf_t done before aliasing write into A
        #pragma unroll
        for (int mi = 0; mi < 4; mi++)
            #pragma unroll
            for (int ni = 0; ni < 4; ni++) {
                int m = tl * 64 + mi*16 + g;
                int n = h * DH + ni*8 + tg*2;
                __nv_bfloat162 p01 = __floats2bfloat162_rn(macc[mi][ni][0], macc[mi][ni][1]);
                __nv_bfloat162 p23 = __floats2bfloat162_rn(macc[mi][ni][2], macc[mi][ni][3]);
                *(__nv_bfloat162*)(xn_s + m * XS + n)       = p01;
                *(__nv_bfloat162*)(xn_s + (m + 8) * XS + n) = p23;
            }
    }
    __syncthreads();

    // ===== Phase 2: out = mixed @ Wp^T + bias + x =====
    #pragma unroll
    for (int mi = 0; mi < 2; mi++)
        #pragma unroll
        for (int ni = 0; ni < 8; ni++)
            #pragma unroll
            for (int k = 0; k < 4; k++) acc[mi][ni][k] = 0.f;
    gemm_phase(smb, g_wp, acc, aB0, aB1, bB, tid);
    __syncthreads();   // all warps done reading B buffers before reuse as fp32 stage

    // epilogue 2: per col-quarter, stage fp32 -> coalesced float4 out
    {
        float* stg = (float*)(sm + SM_B);   // [128][68] fp32
        for (int q = 0; q < 4; q++) {
            if ((warp >> 2) == q) {
                #pragma unroll
                for (int mi = 0; mi < 2; mi++)
                    #pragma unroll
                    for (int ni = 0; ni < 8; ni++) {
                        int m = wm + mi * 16 + g;
                        int e = ni * 8 + tg * 2;
                        stg[m * 68 + e]           = acc[mi][ni][0];
                        stg[m * 68 + e + 1]       = acc[mi][ni][1];
                        stg[(m + 8) * 68 + e]     = acc[mi][ni][2];
                        stg[(m + 8) * 68 + e + 1] = acc[mi][ni][3];
                    }
            }
            __syncthreads();
            #pragma unroll
            for (int it = 0; it < 4; it++) {
                int idx = it * 512 + tid;        // 0..2047
                int row = idx >> 4;              // 0..127
                int c4  = (idx & 15) * 4;
                int tl = row >> 6, v = row & 63;
                int tglob = 2 * tile + tl;
                if (tglob <= 256) {
                    size_t gbase = ((size_t)(b * VV + v) * TT + tglob) * DD + q * 64 + c4;
                    float4 s  = *(float4*)(stg + row * 68 + c4);
                    float4 xr = *(const float4*)(x + gbase);
                    float4 bb = *(const float4*)(b_proj + q * 64 + c4);
                    float4 o;
                    o.x = s.x + bb.x + xr.x;
                    o.y = s.y + bb.y + xr.y;
                    o.z = s.z + bb.z + xr.z;
                    o.w = s.w + bb.w + xr.w;
                    *(float4*)(out + gbase) = o;
                }
            }
            __syncthreads();
        }
    }
}

// ---------------- launch: 4 kernels, fused at index 3 (profiled) ----------------
extern "C" void kernel_launch(void* const* d_in, const int* in_sizes, int n_in,
                              void* d_out, int out_size) {
    const float* x        = (const float*)d_in[0];
    const void*  obs_mask = d_in[1];
    const float* ln_w     = (const float*)d_in[2];
    const float* ln_b     = (const float*)d_in[3];
    const float* w_qkv    = (const float*)d_in[4];
    const float* w_proj   = (const float*)d_in[5];
    const float* b_proj   = (const float*)d_in[6];
    float* out = (float*)d_out;

    cudaFuncSetAttribute(fused_kernel, cudaFuncAttributeMaxDynamicSharedMemorySize, SMEM_TOT);

    ln_kernel<<<dim3(BB*VV, 8), 256>>>(x, obs_mask, ln_w, ln_b);
    qkw_kernel<<<BB*VV, 256>>>(w_qkv, w_proj);
    attn_kernel<<<BB*HH, 256>>>();
    fused_kernel<<<dim3(129, BB), 512, SMEM_TOT>>>(x, b_proj, out);
}

// round 16
// speedup vs baseline: 1.7837x; 1.0097x over previous
#include <cuda_runtime.h>
#include <cuda_bf16.h>
#include <stdint.h>

#define BB 8
#define VV 64
#define TT 257
#define DD 256
#define HH 8
#define DH 32

#define XN_ELEMS (BB*VV*TT*DD)

// ---------------- scratch ----------------
__device__ __align__(128) __nv_bfloat16 g_xn[XN_ELEMS];
__device__ __align__(128) float  g_xsum8[8*BB*VV*DD];
__device__ __align__(128) float  g_cnt8[8*BB*VV];
__device__ __align__(128) float  g_q[BB*VV*DD];
__device__ __align__(128) float  g_k[BB*VV*DD];
__device__ __align__(128) __nv_bfloat16 g_attn[BB*HH*VV*VV];
__device__ __align__(128) __nv_bfloat16 g_wv[DD*DD];    // w_qkv rows 512..767 [e][k]
__device__ __align__(128) __nv_bfloat16 g_wp[DD*DD];    // w_proj [e][k]

// ---------------- helpers ----------------
__device__ __forceinline__ uint32_t smem_u32(const void* p) {
    uint32_t a;
    asm("{ .reg .u64 t; cvta.to.shared.u64 t, %1; cvt.u32.u64 %0, t; }" : "=r"(a) : "l"(p));
    return a;
}
__device__ __forceinline__ void mma16816(float* c, const uint32_t* a, uint32_t b0, uint32_t b1) {
    asm volatile(
        "mma.sync.aligned.m16n8k16.row.col.f32.bf16.bf16.f32 "
        "{%0,%1,%2,%3}, {%4,%5,%6,%7}, {%8,%9}, {%0,%1,%2,%3};"
        : "+f"(c[0]), "+f"(c[1]), "+f"(c[2]), "+f"(c[3])
        : "r"(a[0]), "r"(a[1]), "r"(a[2]), "r"(a[3]), "r"(b0), "r"(b1));
}
__device__ __forceinline__ void ldm_x4(uint32_t* r, uint32_t addr) {
    asm volatile("ldmatrix.sync.aligned.m8n8.x4.shared.b16 {%0,%1,%2,%3}, [%4];"
        : "=r"(r[0]), "=r"(r[1]), "=r"(r[2]), "=r"(r[3]) : "r"(addr));
}
__device__ __forceinline__ void cp_async16(uint32_t smem, const void* gmem) {
    asm volatile("cp.async.cg.shared.global [%0], [%1], 16;\n" :: "r"(smem), "l"(gmem));
}
#define CP_COMMIT() asm volatile("cp.async.commit_group;\n" ::: "memory")
#define CP_WAIT0()  asm volatile("cp.async.wait_group 0;\n" ::: "memory")

__device__ __forceinline__ bool mask_at(const void* m, int idx, int kind) {
    if (kind == 0) return ((const int*)m)[idx] != 0;
    if (kind == 1) return ((const unsigned char*)m)[idx] != 0;
    return ((const float*)m)[idx] != 0.0f;
}

// ---------------- LayerNorm (warp-per-row, mask-kind detect inline) ----------------
__global__ void __launch_bounds__(256)
ln_kernel(const float* __restrict__ x, const void* __restrict__ obs_mask,
          const float* __restrict__ ln_w, const float* __restrict__ ln_b) {
    int bv = blockIdx.x;
    int y  = blockIdx.y;
    int t0 = y * 33;
    int t1 = min(TT, t0 + 33);
    int warp = threadIdx.x >> 5, lane = threadIdx.x & 31;

    __shared__ float wsum[8][DD];
    __shared__ float wcnt[8];
    __shared__ int s_kind;

    if (warp == 0) {
        const unsigned char* m = (const unsigned char*)obs_mask;
        int any = 0, isf = 0;
        for (int j = lane; j < 1024; j += 32) {
            unsigned char b1 = m[j*4+1], b2 = m[j*4+2], b3 = m[j*4+3];
            if (b1 | b2 | b3) any = 1;
            if (b3 == 0x3f) isf = 1;
        }
        unsigned anym = __ballot_sync(0xffffffffu, any);
        unsigned isfm = __ballot_sync(0xffffffffu, isf);
        if (lane == 0) s_kind = isfm ? 2 : (anym ? 1 : 0);
    }
    __syncthreads();
    int kind = s_kind;

    float4 w0  = *(const float4*)(ln_w + lane*4);
    float4 w1  = *(const float4*)(ln_w + 128 + lane*4);
    float4 lb0 = *(const float4*)(ln_b + lane*4);
    float4 lb1 = *(const float4*)(ln_b + 128 + lane*4);

    float acc[8];
    #pragma unroll
    for (int i = 0; i < 8; i++) acc[i] = 0.0f;
    float cnt = 0.0f;

    for (int t = t0 + warp; t < t1; t += 8) {
        size_t base = ((size_t)bv * TT + t) * DD;
        float4 v0 = *(const float4*)(x + base + lane*4);
        float4 v1 = *(const float4*)(x + base + 128 + lane*4);
        float s  = v0.x + v0.y + v0.z + v0.w + v1.x + v1.y + v1.z + v1.w;
        float s2 = v0.x*v0.x + v0.y*v0.y + v0.z*v0.z + v0.w*v0.w
                 + v1.x*v1.x + v1.y*v1.y + v1.z*v1.z + v1.w*v1.w;
        #pragma unroll
        for (int o = 16; o > 0; o >>= 1) {
            s  += __shfl_xor_sync(0xffffffffu, s, o);
            s2 += __shfl_xor_sync(0xffffffffu, s2, o);
        }
        float mu  = s * (1.0f/256.0f);
        float var = s2 * (1.0f/256.0f) - mu * mu;
        float rstd = rsqrtf(var + 1e-5f);

        float xn[8];
        xn[0] = (v0.x - mu) * rstd * w0.x + lb0.x;
        xn[1] = (v0.y - mu) * rstd * w0.y + lb0.y;
        xn[2] = (v0.z - mu) * rstd * w0.z + lb0.z;
        xn[3] = (v0.w - mu) * rstd * w0.w + lb0.w;
        xn[4] = (v1.x - mu) * rstd * w1.x + lb1.x;
        xn[5] = (v1.y - mu) * rstd * w1.y + lb1.y;
        xn[6] = (v1.z - mu) * rstd * w1.z + lb1.z;
        xn[7] = (v1.w - mu) * rstd * w1.w + lb1.w;

        __nv_bfloat162 p0 = __floats2bfloat162_rn(xn[0], xn[1]);
        __nv_bfloat162 p1 = __floats2bfloat162_rn(xn[2], xn[3]);
        __nv_bfloat162 p2 = __floats2bfloat162_rn(xn[4], xn[5]);
        __nv_bfloat162 p3 = __floats2bfloat162_rn(xn[6], xn[7]);
        uint2 u0; u0.x = *(uint32_t*)&p0; u0.y = *(uint32_t*)&p1;
        uint2 u1; u1.x = *(uint32_t*)&p2; u1.y = *(uint32_t*)&p3;
        *(uint2*)(g_xn + base + lane*4)       = u0;
        *(uint2*)(g_xn + base + 128 + lane*4) = u1;

        bool mk = (t == 0) || mask_at(obs_mask, bv * (TT-1) + (t - 1), kind);
        if (mk) {
            #pragma unroll
            for (int i = 0; i < 8; i++) acc[i] += xn[i];
            cnt += 1.0f;
        }
    }
    #pragma unroll
    for (int i = 0; i < 4; i++) {
        wsum[warp][lane*4 + i]       = acc[i];
        wsum[warp][128 + lane*4 + i] = acc[4 + i];
    }
    if (lane == 0) wcnt[warp] = cnt;
    __syncthreads();
    int tid = threadIdx.x;
    float S = 0.f;
    #pragma unroll
    for (int wv = 0; wv < 8; wv++) S += wsum[wv][tid];
    g_xsum8[(y * BB*VV + bv) * DD + tid] = S;
    if (tid == 0) {
        float C = 0.f;
        #pragma unroll
        for (int wv = 0; wv < 8; wv++) C += wcnt[wv];
        g_cnt8[y * BB*VV + bv] = C;
    }
}

// ---------------- q / k projections + weight bf16 conversion ----------------
__global__ void qkw_kernel(const float* __restrict__ w_qkv, const float* __restrict__ w_proj) {
    int bv = blockIdx.x;
    int tid = threadIdx.x;
    {
        int i = blockIdx.x * 256 + tid;
        if (i < DD*DD) {
            g_wv[i] = __float2bfloat16(w_qkv[2*DD*DD + i]);
            g_wp[i] = __float2bfloat16(w_proj[i]);
        }
    }
    __shared__ float xn0[DD], xm[DD];
    xn0[tid] = __bfloat162float(g_xn[(size_t)bv * TT * DD + tid]);
    {
        float S = 0.f, C = 0.f;
        #pragma unroll
        for (int y = 0; y < 8; y++) {
            S += g_xsum8[(y * BB*VV + bv) * DD + tid];
            C += g_cnt8[y * BB*VV + bv];
        }
        xm[tid] = S / C;
    }
    __syncthreads();
    int warp = tid >> 5, lane = tid & 31;
    for (int e = warp; e < DD; e += 8) {
        const float4* wq = (const float4*)(w_qkv + (size_t)e * DD);
        const float4* wk = (const float4*)(w_qkv + (size_t)(DD + e) * DD);
        float q = 0.f, k = 0.f;
        #pragma unroll
        for (int i = lane; i < 64; i += 32) {
            float4 aq = wq[i], ak = wk[i];
            const float* xq = xn0 + i * 4;
            const float* xk = xm + i * 4;
            q += xq[0]*aq.x + xq[1]*aq.y + xq[2]*aq.z + xq[3]*aq.w;
            k += xk[0]*ak.x + xk[1]*ak.y + xk[2]*ak.z + xk[3]*ak.w;
        }
        #pragma unroll
        for (int o = 16; o > 0; o >>= 1) {
            q += __shfl_xor_sync(0xffffffffu, q, o);
            k += __shfl_xor_sync(0xffffffffu, k, o);
        }
        if (lane == 0) { g_q[bv * DD + e] = q; g_k[bv * DD + e] = k; }
    }
}

// ---------------- attention softmax ----------------
__global__ void attn_kernel() {
    int b = blockIdx.x >> 3, h = blockIdx.x & 7;
    __shared__ float qs[VV][33], ks[VV][33];
    __shared__ float lg[VV][65];
    int tid = threadIdx.x;
    for (int i = tid; i < VV * DH; i += 256) {
        int v = i >> 5, dd = i & 31;
        qs[v][dd] = g_q[(b * VV + v) * DD + h * DH + dd];
        ks[v][dd] = g_k[(b * VV + v) * DD + h * DH + dd];
    }
    __syncthreads();
    const float scale = 0.17677669529663687f;
    for (int p = tid; p < VV * VV; p += 256) {
        int i = p >> 6, j = p & 63;
        float s = 0.f;
        #pragma unroll
        for (int c = 0; c < DH; c++) s += qs[i][c] * ks[j][c];
        lg[i][j] = s * scale;
    }
    __syncthreads();
    int warp = tid >> 5, lane = tid & 31;
    for (int r = warp; r < VV; r += 8) {
        float v0 = lg[r][lane], v1 = lg[r][lane + 32];
        float m = fmaxf(v0, v1);
        #pragma unroll
        for (int o = 16; o > 0; o >>= 1) m = fmaxf(m, __shfl_xor_sync(0xffffffffu, m, o));
        float e0 = __expf(v0 - m), e1 = __expf(v1 - m);
        float s = e0 + e1;
        #pragma unroll
        for (int o = 16; o > 0; o >>= 1) s += __shfl_xor_sync(0xffffffffu, s, o);
        float inv = 1.0f / s;
        __nv_bfloat16* ap = g_attn + ((size_t)(b * HH + h) * VV + r) * VV;
        ap[lane]      = __float2bfloat16(e0 * inv);
        ap[lane + 32] = __float2bfloat16(e1 * inv);
    }
}

// ---------------- fused: M=128, 512 threads, 1 CTA/SM, minimal barriers ----------------
// SMEM map (bytes):
//   R1 [0, 67584)        A: xn [128][XS=264] bf16; later mixed (same layout)
//   R2 [67584, 210944):
//      phase 0: Wv full [256][WS=280] bf16 (143360 B, 560B stride, conflict-free)
//      after:   vfT [256][VSTR=136] bf16 @ 67584 (69632 B)   | then fp32 out-stage [128][132]
//               Wp double-buffer 2 x [256][BS2=72] bf16 @ 137216 (73728 B)
#define XS 264
#define WS 280
#define BS2 72
#define VSTR 136
#define STGW 132
#define SM_R1 0
#define SM_R2 67584
#define SM_WP 137216
#define WPBUF 36864
#define SMEM_TOT 210944

__device__ __forceinline__ void stage_wp(uint32_t smb, int kc, int buf, int tid) {
    int e = tid >> 1, half = tid & 1;
    uint32_t dst = smb + SM_WP + buf * WPBUF + (uint32_t)(e * (BS2*2) + half * 64);
    const __nv_bfloat16* src = g_wp + e * DD + kc * 64 + half * 32;
    #pragma unroll
    for (int j = 0; j < 4; j++) cp_async16(dst + j * 16, src + j * 8);
    CP_COMMIT();
}

__global__ void __launch_bounds__(512, 1)
fused_kernel(const float* __restrict__ x, const float* __restrict__ b_proj,
             float* __restrict__ out) {
    const int tile = blockIdx.x;            // t-pair: t = 2*tile + {0,1}
    const int b    = blockIdx.y;
    extern __shared__ __align__(128) char sm[];
    const uint32_t smb = smem_u32(sm);
    __nv_bfloat16* xn_s = (__nv_bfloat16*)(sm + SM_R1);
    __nv_bfloat16* vf_t = (__nv_bfloat16*)(sm + SM_R2);

    const int tid  = threadIdx.x;
    const int warp = tid >> 5, lane = tid & 31;
    const int g = lane >> 2, tg = lane & 3;
    const int wm = (warp & 3) * 32;
    const int wn = (warp >> 2) * 64;

    // ldmatrix base addresses
    const int sel = lane >> 3;
    uint32_t aB0, aB1, bWv[4], bWp[4];
    {
        int arow = wm + (sel & 1) * 8 + (lane & 7);
        uint32_t abase = smb + SM_R1 + (uint32_t)((arow * XS + (sel >> 1) * 8) * 2);
        aB0 = abase;
        aB1 = abase + (uint32_t)(16 * XS * 2);
        int n_off = (lane >> 4) * 8 + (lane & 7);
        int kb = ((lane >> 3) & 1) * 8;
        #pragma unroll
        for (int p = 0; p < 4; p++) {
            bWv[p] = smb + SM_R2 + (uint32_t)(((wn + p * 16 + n_off) * WS  + kb) * 2);
            bWp[p] = smb + SM_WP + (uint32_t)(((wn + p * 16 + n_off) * BS2 + kb) * 2);
        }
    }

    // ---- prologue: stage A (64KB) + full Wv (128KB), single wait ----
    {
        #pragma unroll
        for (int it = 0; it < 8; it++) {
            int idx = it * 512 + tid;            // 0..4095
            int row = idx >> 5, c16 = idx & 31;
            int tl = row >> 6, v = row & 63;
            int tglob = min(2 * tile + tl, 256);
            uint32_t dst = smb + SM_R1 + (uint32_t)(row * XS * 2 + c16 * 16);
            const void* src = g_xn + ((size_t)(b * VV + v) * TT + tglob) * DD + c16 * 8;
            cp_async16(dst, src);
        }
        int row = tid >> 1, half = tid & 1;
        uint32_t dst = smb + SM_R2 + (uint32_t)(row * (WS*2) + half * 256);
        const __nv_bfloat16* src = g_wv + row * DD + half * 128;
        #pragma unroll
        for (int j = 0; j < 16; j++) cp_async16(dst + j * 16, src + j * 8);
        CP_COMMIT();
    }
    CP_WAIT0();
    __syncthreads();

    // ===== Phase 0: vf = xn @ Wv^T — 16 ksteps, zero barriers =====
    float acc[2][8][4];
    #pragma unroll
    for (int mi = 0; mi < 2; mi++)
        #pragma unroll
        for (int ni = 0; ni < 8; ni++)
            #pragma unroll
            for (int k = 0; k < 4; k++) acc[mi][ni][k] = 0.f;

    #pragma unroll
    for (int ks = 0; ks < 16; ks++) {
        uint32_t kbyte = (uint32_t)(ks * 32);
        uint32_t a0[4], a1[4], bf[4][4];
        ldm_x4(a0, aB0 + kbyte);
        ldm_x4(a1, aB1 + kbyte);
        #pragma unroll
        for (int p = 0; p < 4; p++) ldm_x4(bf[p], bWv[p] + kbyte);
        #pragma unroll
        for (int p = 0; p < 4; p++) {
            mma16816(acc[0][2*p],   a0, bf[p][0], bf[p][1]);
            mma16816(acc[1][2*p],   a1, bf[p][0], bf[p][1]);
            mma16816(acc[0][2*p+1], a0, bf[p][2], bf[p][3]);
            mma16816(acc[1][2*p+1], a1, bf[p][2], bf[p][3]);
        }
    }
    __syncthreads();                       // all Wv + A reads retired

    // prefetch Wp chunk 0 (overlaps ep0 + mix; consumed at phase-2 start)
    stage_wp(smb, 0, 0, tid);

    // epilogue 0: acc -> vfT[e][m] (overwrites Wv front)
    #pragma unroll
    for (int mi = 0; mi < 2; mi++)
        #pragma unroll
        for (int ni = 0; ni < 8; ni++) {
            int m = wm + mi * 16 + g;
            int e = wn + ni * 8 + tg * 2;
            vf_t[(e    ) * VSTR + m    ] = __float2bfloat16(acc[mi][ni][0]);
            vf_t[(e + 1) * VSTR + m    ] = __float2bfloat16(acc[mi][ni][1]);
            vf_t[(e    ) * VSTR + m + 8] = __float2bfloat16(acc[mi][ni][2]);
            vf_t[(e + 1) * VSTR + m + 8] = __float2bfloat16(acc[mi][ni][3]);
        }
    __syncthreads();

    // ===== Mix: warp w -> head h = w&7, t-half tl = w>>3 ; 64x32x64 =====
    {
        const int h = warp & 7, tl = warp >> 3;
        float macc[4][4][4];
        #pragma unroll
        for (int mi = 0; mi < 4; mi++)
            #pragma unroll
            for (int ni = 0; ni < 4; ni++)
                #pragma unroll
                for (int k = 0; k < 4; k++) macc[mi][ni][k] = 0.f;

        const __nv_bfloat16* attn_p = g_attn + (size_t)(b * HH + h) * VV * VV;
        #pragma unroll
        for (int ks = 0; ks < 4; ks++) {
            int kk = ks * 16;
            uint32_t a[4][4];
            #pragma unroll
            for (int mi = 0; mi < 4; mi++) {
                const __nv_bfloat16* ap = attn_p + (mi*16 + g) * VV + kk + tg*2;
                a[mi][0] = *(const uint32_t*)(ap);
                a[mi][1] = *(const uint32_t*)(ap + 8 * VV);
                a[mi][2] = *(const uint32_t*)(ap + 8);
                a[mi][3] = *(const uint32_t*)(ap + 8 * VV + 8);
            }
            #pragma unroll
            for (int ni = 0; ni < 4; ni++) {
                const __nv_bfloat16* bp = vf_t + (h * DH + ni*8 + g) * VSTR + tl * 64 + kk + tg*2;
                uint32_t b0 = *(const uint32_t*)(bp);
                uint32_t b1 = *(const uint32_t*)(bp + 8);
                #pragma unroll
                for (int mi = 0; mi < 4; mi++) mma16816(macc[mi][ni], a[mi], b0, b1);
            }
        }
        __syncthreads();   // reads of xn_s/vf_t done before aliasing write into R1
        #pragma unroll
        for (int mi = 0; mi < 4; mi++)
            #pragma unroll
            for (int ni = 0; ni < 4; ni++) {
                int m = tl * 64 + mi*16 + g;
                int n = h * DH + ni*8 + tg*2;
                __nv_bfloat162 p01 = __floats2bfloat162_rn(macc[mi][ni][0], macc[mi][ni][1]);
                __nv_bfloat162 p23 = __floats2bfloat162_rn(macc[mi][ni][2], macc[mi][ni][3]);
                *(__nv_bfloat162*)(xn_s + m * XS + n)       = p01;
                *(__nv_bfloat162*)(xn_s + (m + 8) * XS + n) = p23;
            }
    }
    __syncthreads();

    // ===== Phase 2: out = mixed @ Wp^T, KC=64 double-buffered =====
    #pragma unroll
    for (int mi = 0; mi < 2; mi++)
        #pragma unroll
        for (int ni = 0; ni < 8; ni++)
            #pragma unroll
            for (int k = 0; k < 4; k++) acc[mi][ni][k] = 0.f;

    for (int kc = 0; kc < 4; kc++) {
        CP_WAIT0();
        __syncthreads();
        if (kc < 3) stage_wp(smb, kc + 1, (kc + 1) & 1, tid);
        uint32_t bufo = (uint32_t)((kc & 1) * WPBUF);
        #pragma unroll
        for (int ks = 0; ks < 4; ks++) {
            uint32_t kbyte = (uint32_t)((kc * 64 + ks * 16) * 2);
            uint32_t a0[4], a1[4], bf[4][4];
            ldm_x4(a0, aB0 + kbyte);
            ldm_x4(a1, aB1 + kbyte);
            #pragma unroll
            for (int p = 0; p < 4; p++) ldm_x4(bf[p], bWp[p] + bufo + (uint32_t)(ks * 32));
            #pragma unroll
            for (int p = 0; p < 4; p++) {
                mma16816(acc[0][2*p],   a0, bf[p][0], bf[p][1]);
                mma16816(acc[1][2*p],   a1, bf[p][0], bf[p][1]);
                mma16816(acc[0][2*p+1], a0, bf[p][2], bf[p][3]);
                mma16816(acc[1][2*p+1], a1, bf[p][2], bf[p][3]);
            }
        }
    }

    // ===== Epilogue 2: two col-halves; fp32 stage in dead vfT region =====
    // warps 0..7 own cols [0,128) (wn in {0,64}); warps 8..15 own [128,256).
    {
        float* stg = (float*)(sm + SM_R2);   // [128][STGW=132] f32 (67584 B < 69632)
        #pragma unroll
        for (int hh = 0; hh < 2; hh++) {
            if ((warp >> 3) == hh) {
                #pragma unroll
                for (int mi = 0; mi < 2; mi++)
                    #pragma unroll
                    for (int ni = 0; ni < 8; ni++) {
                        int m  = wm + mi * 16 + g;
                        int lc = (wn - hh * 128) + ni * 8 + tg * 2;
                        stg[m * STGW + lc]           = acc[mi][ni][0];
                        stg[m * STGW + lc + 1]       = acc[mi][ni][1];
                        stg[(m + 8) * STGW + lc]     = acc[mi][ni][2];
                        stg[(m + 8) * STGW + lc + 1] = acc[mi][ni][3];
                    }
            }
            __syncthreads();
            #pragma unroll
            for (int sb = 0; sb < 2; sb++) {
                float4 xv[4];
                size_t gb[4];
                int rows[4], c4s[4];
                bool ok[4];
                #pragma unroll
                for (int it = 0; it < 4; it++) {
                    int idx = (sb * 4 + it) * 512 + tid;   // 0..4095
                    int row = idx >> 5;                     // 0..127
                    int c4  = (idx & 31) * 4;               // 0..124
                    int tl = row >> 6, v = row & 63;
                    int tglob = 2 * tile + tl;
                    ok[it] = (tglob <= 256);
                    rows[it] = row; c4s[it] = c4;
                    gb[it] = ((size_t)(b * VV + v) * TT + tglob) * DD + hh * 128 + c4;
                    if (ok[it]) xv[it] = *(const float4*)(x + gb[it]);
                }
                #pragma unroll
                for (int it = 0; it < 4; it++) {
                    if (ok[it]) {
                        float4 s  = *(float4*)(stg + rows[it] * STGW + c4s[it]);
                        float4 bb = *(const float4*)(b_proj + hh * 128 + c4s[it]);
                        float4 o;
                        o.x = s.x + bb.x + xv[it].x;
                        o.y = s.y + bb.y + xv[it].y;
                        o.z = s.z + bb.z + xv[it].z;
                        o.w = s.w + bb.w + xv[it].w;
                        *(float4*)(out + gb[it]) = o;
                    }
                }
            }
            __syncthreads();
        }
    }
}

// ---------------- launch: 4 kernels, fused at index 3 (profiled) ----------------
extern "C" void kernel_launch(void* const* d_in, const int* in_sizes, int n_in,
                              void* d_out, int out_size) {
    const float* x        = (const float*)d_in[0];
    const void*  obs_mask = d_in[1];
    const float* ln_w     = (const float*)d_in[2];
    const float* ln_b     = (const float*)d_in[3];
    const float* w_qkv    = (const float*)d_in[4];
    const float* w_proj   = (const float*)d_in[5];
    const float* b_proj   = (const float*)d_in[6];
    float* out = (float*)d_out;

    cudaFuncSetAttribute(fused_kernel, cudaFuncAttributeMaxDynamicSharedMemorySize, SMEM_TOT);

    ln_kernel<<<dim3(BB*VV, 8), 256>>>(x, obs_mask, ln_w, ln_b);
    qkw_kernel<<<BB*VV, 256>>>(w_qkv, w_proj);
    attn_kernel<<<BB*HH, 256>>>();
    fused_kernel<<<dim3(129, BB), 512, SMEM_TOT>>>(x, b_proj, out);
}